// round 7
// baseline (speedup 1.0000x reference)
#include <cuda_runtime.h>
#include <cuda_bf16.h>
#include <math.h>
#include <stdint.h>

#define NNODES 8192
#define HDIM   128
#define KNN    16
#define NEDGE  262144
#define NKR    (NNODES*KNN)
#define KSPL   2
#define CPS    (NNODES/KSPL)
#define TPC    (CPS/128)
#define TKEEP  32              // approx survivors per split

// ---------------- scratch (device globals) ----------------
static __device__ float g_h[NNODES*HDIM];
static __device__ float g_nbuf[3][NNODES*HDIM];
static __device__ float g_sn[NNODES];
static __device__ float g_deg[NNODES];
static __device__ float g_dis[NNODES];
static __device__ int   g_knn[NKR];
static __device__ float g_e[3][NNODES*HDIM];
static __device__ float g_r1[NNODES];
static __device__ int   g_pti[KSPL*NNODES*TKEEP];
static __device__ __nv_bfloat16 g_hi[NNODES*HDIM];
static __device__ __nv_bfloat16 g_lo[NNODES*HDIM];
static __device__ float g_R[NNODES*64];
static __device__ float g_S[NNODES*64];
static __device__ float g_wd[128*64];
// CSR
static __device__ int   g_cnt[NNODES];
static __device__ int   g_off[NNODES+1];
static __device__ int   g_cur[NNODES];
static __device__ int   g_esrc[NEDGE];
static __device__ float g_enrm[NEDGE];

// ---------------- helpers ----------------
__device__ __forceinline__ uint32_t smem_u32(const void* p) {
    uint32_t a;
    asm("{ .reg .u64 t; cvta.to.shared.u64 t, %1; cvt.u32.u64 %0, t; }" : "=r"(a) : "l"(p));
    return a;
}
__device__ __forceinline__ void ldm_x4(uint32_t* r, uint32_t addr) {
    asm volatile("ldmatrix.sync.aligned.m8n8.x4.shared.b16 {%0,%1,%2,%3}, [%4];"
        : "=r"(r[0]), "=r"(r[1]), "=r"(r[2]), "=r"(r[3]) : "r"(addr));
}
__device__ __forceinline__ void mma16816(float* c, const uint32_t* a, const uint32_t* b) {
    asm volatile("mma.sync.aligned.m16n8k16.row.col.f32.bf16.bf16.f32 "
        "{%0,%1,%2,%3}, {%4,%5,%6,%7}, {%8,%9}, {%0,%1,%2,%3};"
        : "+f"(c[0]), "+f"(c[1]), "+f"(c[2]), "+f"(c[3])
        : "r"(a[0]), "r"(a[1]), "r"(a[2]), "r"(a[3]), "r"(b[0]), "r"(b[1]));
}
__device__ __forceinline__ __nv_bfloat162 split_hi2(float a, float b) {
    __nv_bfloat162 r; r.x = __float2bfloat16(a); r.y = __float2bfloat16(b); return r;
}
__device__ __forceinline__ __nv_bfloat162 split_lo2(float a, float b, __nv_bfloat162 h) {
    __nv_bfloat162 r;
    r.x = __float2bfloat16(a - __bfloat162float(h.x));
    r.y = __float2bfloat16(b - __bfloat162float(h.y));
    return r;
}

// ---------------- graph prep kernels ----------------
__global__ void k_deg_init() {
    int i = blockIdx.x*blockDim.x + threadIdx.x;
    if (i < NNODES) { g_deg[i] = 1.0f; g_cnt[i] = 0; }
}
__global__ void k_deg(const int* __restrict__ ei, const float* __restrict__ ew) {
    int e = blockIdx.x*blockDim.x + threadIdx.x;
    if (e < NEDGE) {
        atomicAdd(&g_deg[ei[NEDGE + e]], ew[e]);
        atomicAdd(&g_cnt[ei[NEDGE + e]], 1);
    }
}
__global__ void k_dis() {
    int i = blockIdx.x*blockDim.x + threadIdx.x;
    if (i < NNODES) g_dis[i] = rsqrtf(g_deg[i]);
}
__global__ void k_scan() {   // single block, 1024 threads, scans g_cnt[8192]
    __shared__ int ws[32];
    int t = threadIdx.x, lane = t & 31, w = t >> 5;
    int base = t*8;
    int v[8], s = 0;
    #pragma unroll
    for (int i = 0; i < 8; i++) { v[i] = s; s += g_cnt[base + i]; }
    int x = s;
    #pragma unroll
    for (int o = 1; o < 32; o <<= 1) {
        int y = __shfl_up_sync(0xffffffffu, x, o);
        if (lane >= o) x += y;
    }
    if (lane == 31) ws[w] = x;
    __syncthreads();
    if (w == 0) {
        int y = ws[lane];
        #pragma unroll
        for (int o = 1; o < 32; o <<= 1) {
            int z = __shfl_up_sync(0xffffffffu, y, o);
            if (lane >= o) y += z;
        }
        ws[lane] = y;
    }
    __syncthreads();
    int off = x - s + (w ? ws[w-1] : 0);
    #pragma unroll
    for (int i = 0; i < 8; i++) { g_off[base + i] = off + v[i]; g_cur[base + i] = off + v[i]; }
    if (t == 1023) g_off[NNODES] = off + s;
}
__global__ void k_place(const int* __restrict__ ei, const float* __restrict__ ew) {
    int e = blockIdx.x*blockDim.x + threadIdx.x;
    if (e < NEDGE) {
        int s = ei[e], d = ei[NEDGE + e];
        int slot = atomicAdd(&g_cur[d], 1);
        g_esrc[slot] = s;
        g_enrm[slot] = g_dis[s] * ew[e] * g_dis[d];
    }
}

// ---------------- fused GCN aggregate + tanh + sn + split ----------------
__global__ void __launch_bounds__(256) k_gather(const float* __restrict__ bg,
                                                float* __restrict__ out) {
    int wid = threadIdx.x >> 5, lane = threadIdx.x & 31;
    int node = blockIdx.x*8 + wid;
    int c = lane*4;
    float dsq = g_dis[node]; dsq *= dsq;
    float4 v = *(const float4*)&g_h[node*HDIM + c];
    v.x *= dsq; v.y *= dsq; v.z *= dsq; v.w *= dsq;
    int beg = g_off[node], end = g_off[node+1];
    for (int p = beg; p < end; ++p) {
        int s = g_esrc[p];
        float nr = g_enrm[p];
        float4 hv = *(const float4*)&g_h[s*HDIM + c];
        v.x += nr*hv.x; v.y += nr*hv.y; v.z += nr*hv.z; v.w += nr*hv.w;
    }
    float4 b = *(const float4*)&bg[c];
    float t0 = tanhf(v.x + b.x), t1 = tanhf(v.y + b.y);
    float t2 = tanhf(v.z + b.z), t3 = tanhf(v.w + b.w);
    *(float4*)&out[node*HDIM + c] = make_float4(t0, t1, t2, t3);
    float ss = t0*t0 + t1*t1 + t2*t2 + t3*t3;
    #pragma unroll
    for (int o = 16; o; o >>= 1) ss += __shfl_xor_sync(0xffffffffu, ss, o);
    if (lane == 0) g_sn[node] = ss;
    __nv_bfloat162 h01 = split_hi2(t0, t1), h23 = split_hi2(t2, t3);
    __nv_bfloat162 l01 = split_lo2(t0, t1, h01), l23 = split_lo2(t2, t3, h23);
    *(__nv_bfloat162*)&g_hi[node*HDIM + c]     = h01;
    *(__nv_bfloat162*)&g_hi[node*HDIM + c + 2] = h23;
    *(__nv_bfloat162*)&g_lo[node*HDIM + c]     = l01;
    *(__nv_bfloat162*)&g_lo[node*HDIM + c + 2] = l23;
}

__global__ void k_wdiff(const float* __restrict__ w1) {
    int i = blockIdx.x*blockDim.x + threadIdx.x;
    g_wd[i] = w1[i] - w1[128*64 + i];
}

// ---------------- top-K insertion (statically indexed) ----------------
template<int NK>
__device__ __forceinline__ void topk_insert(float (&td)[NK], int (&ti)[NK], float d, int idx) {
    if (d >= td[NK-1]) return;
    #pragma unroll
    for (int p = NK-1; p > 0; --p) {
        bool sh = td[p-1] > d;
        float nd = sh ? td[p-1] : d;
        int   ni = sh ? ti[p-1] : idx;
        if (td[p] > d) { td[p] = nd; ti[p] = ni; }
    }
    if (td[0] > d) { td[0] = d; ti[0] = idx; }
}

// ---------------- approx kNN: pure-bf16 Gram + top-32 ----------------
#define SSTR    136
#define SM_AH   0
#define SM_BH   34816
#define SM_DIST 69632
#define SM_SNC  137216
#define KNN_SMEM 137728

__device__ __forceinline__ void load_tile_hi(char* sm, uint32_t ohi, int node0, int tid) {
    const uint4* HI = (const uint4*)g_hi;
    #pragma unroll
    for (int it = 0; it < 8; ++it) {
        int idx = tid + it*256;
        int row = idx >> 4;
        int c8  = idx & 15;
        uint32_t so = (uint32_t)(row*SSTR + c8*8)*2;
        size_t gi = ((size_t)(node0 + row)*HDIM + c8*8) >> 3;
        *(uint4*)(sm + ohi + so) = HI[gi];
    }
}

__global__ void __launch_bounds__(256) k_knn_mma() {
    extern __shared__ char sm[];
    const uint32_t smb = smem_u32(sm);
    const int tid = threadIdx.x, wid = tid >> 5, lane = tid & 31;
    const int wm = wid >> 1, wn = wid & 1;
    const int q0 = blockIdx.x * 128;
    const int c0 = blockIdx.y * CPS;

    load_tile_hi(sm, SM_AH, q0, tid);

    float td[TKEEP]; int ti[TKEEP];
    #pragma unroll
    for (int j = 0; j < TKEEP; j++) { td[j] = 3.0e38f; ti[j] = 0; }

    const uint32_t a_off = (uint32_t)((32*wm + (lane & 15))*SSTR + (lane >> 4)*8) * 2;
    const uint32_t b_off = (uint32_t)((64*wn + (lane >> 4)*8 + (lane & 7))*SSTR
                                      + ((lane >> 3) & 1)*8) * 2;
    float* dist = (float*)(sm + SM_DIST);
    float* snc  = (float*)(sm + SM_SNC);

    for (int t = 0; t < TPC; ++t) {
        __syncthreads();
        load_tile_hi(sm, SM_BH, c0 + t*128, tid);
        if (tid < 128) snc[tid] = g_sn[c0 + t*128 + tid];
        __syncthreads();

        float acc[2][8][4];
        #pragma unroll
        for (int mf = 0; mf < 2; mf++)
            #pragma unroll
            for (int nf = 0; nf < 8; nf++)
                #pragma unroll
                for (int v = 0; v < 4; v++) acc[mf][nf][v] = 0.f;

        const uint32_t abase = smb + SM_AH + a_off;
        const uint32_t bbase = smb + SM_BH + b_off;
        #pragma unroll
        for (int ks = 0; ks < 8; ++ks) {
            uint32_t a0[4], a1[4];
            ldm_x4(a0, abase + ks*32);
            ldm_x4(a1, abase + ks*32 + 16*SSTR*2);
            #pragma unroll
            for (int nf = 0; nf < 4; ++nf) {
                uint32_t b[4];
                ldm_x4(b, bbase + ks*32 + nf*16*SSTR*2);
                mma16816(acc[0][nf*2],   a0, b);
                mma16816(acc[0][nf*2+1], a0, b + 2);
                mma16816(acc[1][nf*2],   a1, b);
                mma16816(acc[1][nf*2+1], a1, b + 2);
            }
        }

        {
            const int r0 = 32*wm + (lane >> 2);
            const int cb = 64*wn + (lane & 3)*2;
            #pragma unroll
            for (int mf = 0; mf < 2; mf++)
                #pragma unroll
                for (int nf = 0; nf < 8; nf++) {
                    float2 lo = { acc[mf][nf][0], acc[mf][nf][1] };
                    float2 hi = { acc[mf][nf][2], acc[mf][nf][3] };
                    *(float2*)&dist[(r0 + mf*16    )*132 + cb + nf*8] = lo;
                    *(float2*)&dist[(r0 + mf*16 + 8)*132 + cb + nf*8] = hi;
                }
        }
        __syncthreads();

        if (tid < 128) {
            const int cbase = c0 + t*128;
            float worst = td[TKEEP-1];
            #pragma unroll 4
            for (int c = 0; c < 128; c++) {
                float d = snc[c] - 2.0f*dist[tid*132 + c];
                if (d < worst) { topk_insert<TKEEP>(td, ti, d, cbase + c); worst = td[TKEEP-1]; }
            }
        }
    }

    if (tid < 128) {
        int q = q0 + tid;
        #pragma unroll
        for (int j = 0; j < TKEEP; j++)
            g_pti[(q*KSPL + blockIdx.y)*TKEEP + j] = ti[j];
    }
}

// ---------------- exact refine: fp32 distances on 64 survivors ----------------
__global__ void __launch_bounds__(256) k_refine(const float* __restrict__ X) {
    int wid = threadIdx.x >> 5, lane = threadIdx.x & 31;
    int q = blockIdx.x*8 + wid;
    float4 xi = *(const float4*)&X[(size_t)q*HDIM + lane*4];
    float dloc[2]; int iloc[2];
    dloc[0] = dloc[1] = 3.0e38f;
    iloc[0] = iloc[1] = 0x7fffffff;
    #pragma unroll 4
    for (int c = 0; c < 2*TKEEP; c++) {
        int j = g_pti[(q*KSPL + (c >> 5))* TKEEP + (c & (TKEEP-1))];
        float4 xj = *(const float4*)&X[(size_t)j*HDIM + lane*4];
        float p = xi.x*xj.x + xi.y*xj.y + xi.z*xj.z + xi.w*xj.w;
        #pragma unroll
        for (int o = 16; o; o >>= 1) p += __shfl_xor_sync(0xffffffffu, p, o);
        float d = g_sn[j] - 2.0f*p;    // sn_i constant per row: ranking-invariant
        if (lane == (c & 31)) { dloc[c >> 5] = d; iloc[c >> 5] = j; }
    }
    // extract 16 smallest (ties: lower index) — set order irrelevant downstream
    for (int r = 0; r < KNN; r++) {
        float d = dloc[0]; int idx = iloc[0]; int sl = 0;
        if (dloc[1] < d || (dloc[1] == d && iloc[1] < idx)) { d = dloc[1]; idx = iloc[1]; sl = 1; }
        float dw = d; int iw = idx;
        #pragma unroll
        for (int o = 16; o; o >>= 1) {
            float od = __shfl_xor_sync(0xffffffffu, dw, o);
            int   oi = __shfl_xor_sync(0xffffffffu, iw, o);
            if (od < dw || (od == dw && oi < iw)) { dw = od; iw = oi; }
        }
        if (d == dw && idx == iw) dloc[sl] = 3.0e38f;
        if (lane == 0) g_knn[q*KNN + r] = iw;
    }
}

// ---------------- fused EdgeConv MLP, HMMA bf16-split ----------------
#define ESTR1    72
#define ESTR2    136
#define SM_A1H   0
#define SM_A1L   18432
#define SM_W2H   36864
#define SM_W2L   55296
#define SM_W3H   0
#define SM_W3L   34816
#define SM_A2H   73728
#define SM_A2L   108544
#define SM_JIDX  143360
#define EDGE_SMEM (143360 + 512)

__global__ void __launch_bounds__(256) k_edge(
        const float* __restrict__ R, const float* __restrict__ S,
        const float* __restrict__ w2, const float* __restrict__ b2,
        const float* __restrict__ w3, const float* __restrict__ b3,
        float* __restrict__ E)
{
    extern __shared__ char sm[];
    const uint32_t smb = smem_u32(sm);
    const int tid = threadIdx.x, wid = tid >> 5, lane = tid & 31;
    const int wm = wid >> 1, wn = wid & 1;
    const int r0 = blockIdx.x * 128;
    int* jidx = (int*)(sm + SM_JIDX);

    if (tid < 128) jidx[tid] = g_knn[r0 + tid];

    {
        __nv_bfloat16* W2H = (__nv_bfloat16*)(sm + SM_W2H);
        __nv_bfloat16* W2L = (__nv_bfloat16*)(sm + SM_W2L);
        #pragma unroll
        for (int i = 0; i < 32; i++) {
            int e = tid + i*256;
            int k = e >> 7, n = e & 127;
            float v = w2[e];
            __nv_bfloat16 h = __float2bfloat16(v);
            W2H[n*ESTR1 + k] = h;
            W2L[n*ESTR1 + k] = __float2bfloat16(v - __bfloat162float(h));
        }
    }
    __syncthreads();

    {
        __nv_bfloat16* A1H = (__nv_bfloat16*)(sm + SM_A1H);
        __nv_bfloat16* A1L = (__nv_bfloat16*)(sm + SM_A1L);
        int row = tid >> 1;
        int cb = (tid & 1) * 32;
        int i = (r0 + row) >> 4;
        int j = jidx[row];
        const float* Ri = &R[(size_t)i*64 + cb];
        const float* Sj = &S[(size_t)j*64 + cb];
        #pragma unroll
        for (int c = 0; c < 32; c += 4) {
            float4 rv = *(const float4*)(Ri + c);
            float4 sv = *(const float4*)(Sj + c);
            float h0 = fmaxf(rv.x + sv.x, 0.f), h1 = fmaxf(rv.y + sv.y, 0.f);
            float h2 = fmaxf(rv.z + sv.z, 0.f), h3 = fmaxf(rv.w + sv.w, 0.f);
            __nv_bfloat162 a01 = split_hi2(h0, h1), a23 = split_hi2(h2, h3);
            *(__nv_bfloat162*)&A1H[row*ESTR1 + cb + c]     = a01;
            *(__nv_bfloat162*)&A1H[row*ESTR1 + cb + c + 2] = a23;
            *(__nv_bfloat162*)&A1L[row*ESTR1 + cb + c]     = split_lo2(h0, h1, a01);
            *(__nv_bfloat162*)&A1L[row*ESTR1 + cb + c + 2] = split_lo2(h2, h3, a23);
        }
    }
    __syncthreads();

    const uint32_t a_off2 = (uint32_t)((32*wm + (lane & 15))*ESTR1 + (lane >> 4)*8) * 2;
    const uint32_t b_off2 = (uint32_t)((64*wn + (lane >> 4)*8 + (lane & 7))*ESTR1
                                       + ((lane >> 3) & 1)*8) * 2;

    float acc[2][8][4];
    #pragma unroll
    for (int mf = 0; mf < 2; mf++)
        #pragma unroll
        for (int nf = 0; nf < 8; nf++)
            #pragma unroll
            for (int v = 0; v < 4; v++) acc[mf][nf][v] = 0.f;

    #pragma unroll
    for (int term = 0; term < 3; ++term) {
        const uint32_t abase = smb + (term == 2 ? SM_A1L : SM_A1H) + a_off2;
        const uint32_t bbase = smb + (term == 1 ? SM_W2L : SM_W2H) + b_off2;
        #pragma unroll
        for (int ks = 0; ks < 4; ++ks) {
            uint32_t a0[4], a1[4];
            ldm_x4(a0, abase + ks*32);
            ldm_x4(a1, abase + ks*32 + 16*ESTR1*2);
            #pragma unroll
            for (int nf = 0; nf < 4; ++nf) {
                uint32_t b[4];
                ldm_x4(b, bbase + ks*32 + nf*16*ESTR1*2);
                mma16816(acc[0][nf*2],   a0, b);
                mma16816(acc[0][nf*2+1], a0, b + 2);
                mma16816(acc[1][nf*2],   a1, b);
                mma16816(acc[1][nf*2+1], a1, b + 2);
            }
        }
    }
    __syncthreads();

    {
        __nv_bfloat16* A2H = (__nv_bfloat16*)(sm + SM_A2H);
        __nv_bfloat16* A2L = (__nv_bfloat16*)(sm + SM_A2L);
        const int re = 32*wm + (lane >> 2);
        const int ce = 64*wn + (lane & 3)*2;
        #pragma unroll
        for (int mf = 0; mf < 2; mf++)
            #pragma unroll
            for (int nf = 0; nf < 8; nf++) {
                int r = re + mf*16;
                int c = ce + nf*8;
                float v0 = fmaxf(acc[mf][nf][0] + b2[c],   0.f);
                float v1 = fmaxf(acc[mf][nf][1] + b2[c+1], 0.f);
                float v2 = fmaxf(acc[mf][nf][2] + b2[c],   0.f);
                float v3 = fmaxf(acc[mf][nf][3] + b2[c+1], 0.f);
                __nv_bfloat162 h01 = split_hi2(v0, v1), h23 = split_hi2(v2, v3);
                *(__nv_bfloat162*)&A2H[r*ESTR2 + c]       = h01;
                *(__nv_bfloat162*)&A2L[r*ESTR2 + c]       = split_lo2(v0, v1, h01);
                *(__nv_bfloat162*)&A2H[(r+8)*ESTR2 + c]   = h23;
                *(__nv_bfloat162*)&A2L[(r+8)*ESTR2 + c]   = split_lo2(v2, v3, h23);
            }
    }
    {
        __nv_bfloat16* W3H = (__nv_bfloat16*)(sm + SM_W3H);
        __nv_bfloat16* W3L = (__nv_bfloat16*)(sm + SM_W3L);
        #pragma unroll
        for (int i = 0; i < 64; i++) {
            int e = tid + i*256;
            int k = e >> 7, n = e & 127;
            float v = w3[e];
            __nv_bfloat16 h = __float2bfloat16(v);
            W3H[n*ESTR2 + k] = h;
            W3L[n*ESTR2 + k] = __float2bfloat16(v - __bfloat162float(h));
        }
    }
    __syncthreads();

    #pragma unroll
    for (int mf = 0; mf < 2; mf++)
        #pragma unroll
        for (int nf = 0; nf < 8; nf++)
            #pragma unroll
            for (int v = 0; v < 4; v++) acc[mf][nf][v] = 0.f;

    const uint32_t a_off3 = (uint32_t)((32*wm + (lane & 15))*ESTR2 + (lane >> 4)*8) * 2;
    const uint32_t b_off3 = (uint32_t)((64*wn + (lane >> 4)*8 + (lane & 7))*ESTR2
                                       + ((lane >> 3) & 1)*8) * 2;
    #pragma unroll
    for (int term = 0; term < 3; ++term) {
        const uint32_t abase = smb + (term == 2 ? SM_A2L : SM_A2H) + a_off3;
        const uint32_t bbase = smb + (term == 1 ? SM_W3L : SM_W3H) + b_off3;
        #pragma unroll
        for (int ks = 0; ks < 8; ++ks) {
            uint32_t a0[4], a1[4];
            ldm_x4(a0, abase + ks*32);
            ldm_x4(a1, abase + ks*32 + 16*ESTR2*2);
            #pragma unroll
            for (int nf = 0; nf < 4; ++nf) {
                uint32_t b[4];
                ldm_x4(b, bbase + ks*32 + nf*16*ESTR2*2);
                mma16816(acc[0][nf*2],   a0, b);
                mma16816(acc[0][nf*2+1], a0, b + 2);
                mma16816(acc[1][nf*2],   a1, b);
                mma16816(acc[1][nf*2+1], a1, b + 2);
            }
        }
    }

    {
        const int ce = 64*wn + (lane & 3)*2;
        #pragma unroll
        for (int mf = 0; mf < 2; mf++) {
            int node = blockIdx.x*8 + 2*wm + mf;
            #pragma unroll
            for (int nf = 0; nf < 8; nf++) {
                float v0 = fmaxf(acc[mf][nf][0], acc[mf][nf][2]);
                float v1 = fmaxf(acc[mf][nf][1], acc[mf][nf][3]);
                #pragma unroll
                for (int o = 4; o < 32; o <<= 1) {
                    v0 = fmaxf(v0, __shfl_xor_sync(0xffffffffu, v0, o));
                    v1 = fmaxf(v1, __shfl_xor_sync(0xffffffffu, v1, o));
                }
                if ((lane >> 2) == 0) {
                    int c = ce + nf*8;
                    E[(size_t)node*128 + c]     = v0 + b3[c];
                    E[(size_t)node*128 + c + 1] = v1 + b3[c+1];
                }
            }
        }
    }
}

// ---------------- SIMT SGEMM (GCN + R/S precompute) ----------------
template<int BN, int TN, int EPI>
__global__ __launch_bounds__(256) void k_gemm(const float* __restrict__ A,
        const float* __restrict__ B, const float* __restrict__ bias,
        float* __restrict__ C, int Kd)
{
    constexpr int BM = 128, BK = 16, TM = 8;
    __shared__ float As[BK][BM + 4];
    __shared__ float Bs[BK][BN + 4];
    const int tid = threadIdx.x;
    const int tx = tid & 15, ty = tid >> 4;
    const int r0 = blockIdx.x * BM;

    float acc[TM][TN];
    #pragma unroll
    for (int m = 0; m < TM; m++)
        #pragma unroll
        for (int n = 0; n < TN; n++) acc[m][n] = 0.f;

    for (int kb = 0; kb < Kd; kb += BK) {
        #pragma unroll
        for (int i = 0; i < 2; i++) {
            int f = tid + i*256;
            int r = f >> 2, c4 = f & 3;
            float4 v = *(const float4*)&A[(size_t)(r0 + r)*Kd + kb + c4*4];
            As[c4*4+0][r] = v.x; As[c4*4+1][r] = v.y;
            As[c4*4+2][r] = v.z; As[c4*4+3][r] = v.w;
        }
        constexpr int BF4 = BK*BN/4;
        #pragma unroll
        for (int i = 0; i < BF4/256; i++) {
            int f = tid + i*256;
            int r = f / (BN/4), c4 = f % (BN/4);
            *(float4*)&Bs[r][c4*4] = *(const float4*)&B[(size_t)(kb + r)*BN + c4*4];
        }
        __syncthreads();
        #pragma unroll
        for (int kk = 0; kk < BK; kk++) {
            float a[TM], b[TN];
            *(float4*)&a[0] = *(const float4*)&As[kk][ty*TM];
            *(float4*)&a[4] = *(const float4*)&As[kk][ty*TM + 4];
            #pragma unroll
            for (int n = 0; n < TN; n += 4)
                *(float4*)&b[n] = *(const float4*)&Bs[kk][tx*TN + n];
            #pragma unroll
            for (int m = 0; m < TM; m++)
                #pragma unroll
                for (int n = 0; n < TN; n++) acc[m][n] += a[m] * b[n];
        }
        __syncthreads();
    }

    #pragma unroll
    for (int m = 0; m < TM; m++) {
        size_t r = r0 + ty*TM + m;
        #pragma unroll
        for (int n = 0; n < TN; n += 4) {
            float4 v;
            v.x = acc[m][n]; v.y = acc[m][n+1]; v.z = acc[m][n+2]; v.w = acc[m][n+3];
            if constexpr (EPI == 1 || EPI == 3) {
                int c = tx*TN + n;
                v.x += bias[c]; v.y += bias[c+1]; v.z += bias[c+2]; v.w += bias[c+3];
                if constexpr (EPI == 1) {
                    v.x = fmaxf(v.x, 0.f); v.y = fmaxf(v.y, 0.f);
                    v.z = fmaxf(v.z, 0.f); v.w = fmaxf(v.w, 0.f);
                }
            }
            *(float4*)&C[r*BN + tx*TN + n] = v;
        }
    }
}

// ---------------- epilogue kernels ----------------
__global__ void k_rownorm() {
    int w = threadIdx.x >> 5, lane = threadIdx.x & 31;
    int i = blockIdx.x*8 + w;
    float4 e = *(const float4*)&g_e[0][i*HDIM + lane*4];
    float4 n = *(const float4*)&g_nbuf[0][i*HDIM + lane*4];
    float a = e.x + n.x, b = e.y + n.y, c = e.z + n.z, d = e.w + n.w;
    float s = a*a + b*b + c*c + d*d;
    #pragma unroll
    for (int o = 16; o; o >>= 1) s += __shfl_xor_sync(0xffffffffu, s, o);
    if (lane == 0) g_r1[i] = sqrtf(s);
}

__global__ void k_final(float* __restrict__ out) {
    int w = threadIdx.x >> 5, lane = threadIdx.x & 31;
    int i = blockIdx.x*8 + w;
    float r = g_r1[i];
    float4 e2 = *(const float4*)&g_e[1][i*HDIM + lane*4];
    float4 n2 = *(const float4*)&g_nbuf[1][i*HDIM + lane*4];
    float4 e3 = *(const float4*)&g_e[2][i*HDIM + lane*4];
    float4 n3 = *(const float4*)&g_nbuf[2][i*HDIM + lane*4];
    float v0 = r * (e2.x + n2.x) * (e3.x + n3.x);
    float v1 = r * (e2.y + n2.y) * (e3.y + n3.y);
    float v2 = r * (e2.z + n2.z) * (e3.z + n3.z);
    float v3 = r * (e2.w + n2.w) * (e3.w + n3.w);
    float m = fmaxf(fmaxf(v0, v1), fmaxf(v2, v3));
    #pragma unroll
    for (int o = 16; o; o >>= 1) m = fmaxf(m, __shfl_xor_sync(0xffffffffu, m, o));
    float s = expf(v0 - m) + expf(v1 - m) + expf(v2 - m) + expf(v3 - m);
    #pragma unroll
    for (int o = 16; o; o >>= 1) s += __shfl_xor_sync(0xffffffffu, s, o);
    float lse = m + logf(s);
    float4 ov = { v0 - lse, v1 - lse, v2 - lse, v3 - lse };
    *(float4*)&out[i*HDIM + lane*4] = ov;
}

// ---------------- launch ----------------
extern "C" void kernel_launch(void* const* d_in, const int* in_sizes, int n_in,
                              void* d_out, int out_size) {
    const float* x  = (const float*)d_in[0];
    const int*   ei = (const int*)  d_in[1];
    const float* ew = (const float*)d_in[2];
    const float* wg[3] = {(const float*)d_in[3], (const float*)d_in[5], (const float*)d_in[7]};
    const float* bg[3] = {(const float*)d_in[4], (const float*)d_in[6], (const float*)d_in[8]};

    float *p_h, *p_n, *p_e, *p_R, *p_S, *p_wd;
    cudaGetSymbolAddress((void**)&p_h,  g_h);
    cudaGetSymbolAddress((void**)&p_n,  g_nbuf);
    cudaGetSymbolAddress((void**)&p_e,  g_e);
    cudaGetSymbolAddress((void**)&p_R,  g_R);
    cudaGetSymbolAddress((void**)&p_S,  g_S);
    cudaGetSymbolAddress((void**)&p_wd, g_wd);

    cudaFuncSetAttribute(k_knn_mma, cudaFuncAttributeMaxDynamicSharedMemorySize, KNN_SMEM);
    cudaFuncSetAttribute(k_edge,    cudaFuncAttributeMaxDynamicSharedMemorySize, EDGE_SMEM);

    // graph prep (once)
    k_deg_init<<<NNODES/256, 256>>>();
    k_deg<<<NEDGE/256, 256>>>(ei, ew);
    k_dis<<<NNODES/256, 256>>>();
    k_scan<<<1, 1024>>>();
    k_place<<<NEDGE/256, 256>>>(ei, ew);

    const float* cur = x;
    for (int L = 0; L < 3; L++) {
        float* nL = p_n + (size_t)L * NNODES * HDIM;
        float* eL = p_e + (size_t)L * NNODES * HDIM;
        const float* w1 = (const float*)d_in[9 + L*6 + 0];
        const float* b1 = (const float*)d_in[9 + L*6 + 1];
        const float* w2 = (const float*)d_in[9 + L*6 + 2];
        const float* b2 = (const float*)d_in[9 + L*6 + 3];
        const float* w3 = (const float*)d_in[9 + L*6 + 4];
        const float* b3 = (const float*)d_in[9 + L*6 + 5];

        // GCN
        k_gemm<128,8,0><<<NNODES/128, 256>>>(cur, wg[L], nullptr, p_h, 128);
        k_gather<<<NNODES/8, 256>>>(bg[L], nL);

        // kNN: approx bf16 filter + exact fp32 refine
        k_knn_mma<<<dim3(NNODES/128, KSPL), 256, KNN_SMEM>>>();
        k_refine<<<NNODES/8, 256>>>(nL);

        // EdgeConv
        k_wdiff<<<8192/256, 256>>>(w1);
        k_gemm<64,4,3><<<NNODES/128, 256>>>(nL, p_wd,        b1,      p_R, 128);
        k_gemm<64,4,0><<<NNODES/128, 256>>>(nL, w1 + 128*64, nullptr, p_S, 128);
        k_edge<<<NKR/128, 256, EDGE_SMEM>>>(p_R, p_S, w2, b2, w3, b3, eL);

        cur = nL;
    }

    k_rownorm<<<NNODES/8, 256>>>();
    k_final<<<NNODES/8, 256>>>((float*)d_out);
}

// round 8
// speedup vs baseline: 1.3966x; 1.3966x over previous
#include <cuda_runtime.h>
#include <cuda_bf16.h>
#include <math.h>
#include <stdint.h>

#define NNODES 8192
#define HDIM   128
#define KNN    16
#define NEDGE  262144
#define NKR    (NNODES*KNN)
#define KSPL   2
#define CPS    (NNODES/KSPL)
#define TPC    (CPS/128)
#define QKEEP  16              // per-quarter survivors (split x half-row)

// ---------------- scratch (device globals) ----------------
static __device__ float g_h[NNODES*HDIM];
static __device__ float g_nbuf[3][NNODES*HDIM];
static __device__ float g_sn[NNODES];
static __device__ float g_deg[NNODES];
static __device__ float g_dis[NNODES];
static __device__ int   g_knn[NKR];
static __device__ float g_e[3][NNODES*HDIM];
static __device__ float g_r1[NNODES];
static __device__ int   g_pti[KSPL*NNODES*2*QKEEP];
static __device__ __nv_bfloat16 g_hi[NNODES*HDIM];
static __device__ __nv_bfloat16 g_lo[NNODES*HDIM];
static __device__ float g_R[NNODES*64];
static __device__ float g_S[NNODES*64];
static __device__ float g_wd[128*64];
// CSR
static __device__ int   g_cnt[NNODES];
static __device__ int   g_off[NNODES+1];
static __device__ int   g_cur[NNODES];
static __device__ int   g_esrc[NEDGE];
static __device__ float g_enrm[NEDGE];

// ---------------- helpers ----------------
__device__ __forceinline__ uint32_t smem_u32(const void* p) {
    uint32_t a;
    asm("{ .reg .u64 t; cvta.to.shared.u64 t, %1; cvt.u32.u64 %0, t; }" : "=r"(a) : "l"(p));
    return a;
}
__device__ __forceinline__ void ldm_x4(uint32_t* r, uint32_t addr) {
    asm volatile("ldmatrix.sync.aligned.m8n8.x4.shared.b16 {%0,%1,%2,%3}, [%4];"
        : "=r"(r[0]), "=r"(r[1]), "=r"(r[2]), "=r"(r[3]) : "r"(addr));
}
__device__ __forceinline__ void mma16816(float* c, const uint32_t* a, const uint32_t* b) {
    asm volatile("mma.sync.aligned.m16n8k16.row.col.f32.bf16.bf16.f32 "
        "{%0,%1,%2,%3}, {%4,%5,%6,%7}, {%8,%9}, {%0,%1,%2,%3};"
        : "+f"(c[0]), "+f"(c[1]), "+f"(c[2]), "+f"(c[3])
        : "r"(a[0]), "r"(a[1]), "r"(a[2]), "r"(a[3]), "r"(b[0]), "r"(b[1]));
}
__device__ __forceinline__ __nv_bfloat162 split_hi2(float a, float b) {
    __nv_bfloat162 r; r.x = __float2bfloat16(a); r.y = __float2bfloat16(b); return r;
}
__device__ __forceinline__ __nv_bfloat162 split_lo2(float a, float b, __nv_bfloat162 h) {
    __nv_bfloat162 r;
    r.x = __float2bfloat16(a - __bfloat162float(h.x));
    r.y = __float2bfloat16(b - __bfloat162float(h.y));
    return r;
}

// ---------------- graph prep kernels ----------------
__global__ void k_deg_init() {
    int i = blockIdx.x*blockDim.x + threadIdx.x;
    if (i < NNODES) { g_deg[i] = 1.0f; g_cnt[i] = 0; }
}
__global__ void k_deg(const int* __restrict__ ei, const float* __restrict__ ew) {
    int e = blockIdx.x*blockDim.x + threadIdx.x;
    if (e < NEDGE) {
        atomicAdd(&g_deg[ei[NEDGE + e]], ew[e]);
        atomicAdd(&g_cnt[ei[NEDGE + e]], 1);
    }
}
__global__ void k_dis() {
    int i = blockIdx.x*blockDim.x + threadIdx.x;
    if (i < NNODES) g_dis[i] = rsqrtf(g_deg[i]);
}
__global__ void k_scan() {
    __shared__ int ws[32];
    int t = threadIdx.x, lane = t & 31, w = t >> 5;
    int base = t*8;
    int v[8], s = 0;
    #pragma unroll
    for (int i = 0; i < 8; i++) { v[i] = s; s += g_cnt[base + i]; }
    int x = s;
    #pragma unroll
    for (int o = 1; o < 32; o <<= 1) {
        int y = __shfl_up_sync(0xffffffffu, x, o);
        if (lane >= o) x += y;
    }
    if (lane == 31) ws[w] = x;
    __syncthreads();
    if (w == 0) {
        int y = ws[lane];
        #pragma unroll
        for (int o = 1; o < 32; o <<= 1) {
            int z = __shfl_up_sync(0xffffffffu, y, o);
            if (lane >= o) y += z;
        }
        ws[lane] = y;
    }
    __syncthreads();
    int off = x - s + (w ? ws[w-1] : 0);
    #pragma unroll
    for (int i = 0; i < 8; i++) { g_off[base + i] = off + v[i]; g_cur[base + i] = off + v[i]; }
    if (t == 1023) g_off[NNODES] = off + s;
}
__global__ void k_place(const int* __restrict__ ei, const float* __restrict__ ew) {
    int e = blockIdx.x*blockDim.x + threadIdx.x;
    if (e < NEDGE) {
        int s = ei[e], d = ei[NEDGE + e];
        int slot = atomicAdd(&g_cur[d], 1);
        g_esrc[slot] = s;
        g_enrm[slot] = g_dis[s] * ew[e] * g_dis[d];
    }
}

// ---------------- fused GCN aggregate + tanh + sn + split ----------------
__global__ void __launch_bounds__(256) k_gather(const float* __restrict__ bg,
                                                float* __restrict__ out) {
    int wid = threadIdx.x >> 5, lane = threadIdx.x & 31;
    int node = blockIdx.x*8 + wid;
    int c = lane*4;
    float dsq = g_dis[node]; dsq *= dsq;
    float4 v = *(const float4*)&g_h[node*HDIM + c];
    v.x *= dsq; v.y *= dsq; v.z *= dsq; v.w *= dsq;
    int beg = g_off[node], end = g_off[node+1];
    for (int p = beg; p < end; ++p) {
        int s = g_esrc[p];
        float nr = g_enrm[p];
        float4 hv = *(const float4*)&g_h[s*HDIM + c];
        v.x += nr*hv.x; v.y += nr*hv.y; v.z += nr*hv.z; v.w += nr*hv.w;
    }
    float4 b = *(const float4*)&bg[c];
    float t0 = tanhf(v.x + b.x), t1 = tanhf(v.y + b.y);
    float t2 = tanhf(v.z + b.z), t3 = tanhf(v.w + b.w);
    *(float4*)&out[node*HDIM + c] = make_float4(t0, t1, t2, t3);
    float ss = t0*t0 + t1*t1 + t2*t2 + t3*t3;
    #pragma unroll
    for (int o = 16; o; o >>= 1) ss += __shfl_xor_sync(0xffffffffu, ss, o);
    if (lane == 0) g_sn[node] = ss;
    __nv_bfloat162 h01 = split_hi2(t0, t1), h23 = split_hi2(t2, t3);
    __nv_bfloat162 l01 = split_lo2(t0, t1, h01), l23 = split_lo2(t2, t3, h23);
    *(__nv_bfloat162*)&g_hi[node*HDIM + c]     = h01;
    *(__nv_bfloat162*)&g_hi[node*HDIM + c + 2] = h23;
    *(__nv_bfloat162*)&g_lo[node*HDIM + c]     = l01;
    *(__nv_bfloat162*)&g_lo[node*HDIM + c + 2] = l23;
}

__global__ void k_wdiff(const float* __restrict__ w1) {
    int i = blockIdx.x*blockDim.x + threadIdx.x;
    g_wd[i] = w1[i] - w1[128*64 + i];
}

// ---------------- top-K insertion (statically indexed) ----------------
template<int NK>
__device__ __forceinline__ void topk_insert(float (&td)[NK], int (&ti)[NK], float d, int idx) {
    if (d >= td[NK-1]) return;
    #pragma unroll
    for (int p = NK-1; p > 0; --p) {
        bool sh = td[p-1] > d;
        float nd = sh ? td[p-1] : d;
        int   ni = sh ? ti[p-1] : idx;
        if (td[p] > d) { td[p] = nd; ti[p] = ni; }
    }
    if (td[0] > d) { td[0] = d; ti[0] = idx; }
}

// ---------------- approx kNN: pure-bf16 Gram + 256-thread quarter scan ----------------
#define SSTR    136
#define SM_AH   0
#define SM_BH   34816
#define SM_DIST 69632
#define SM_SNC  137216
#define KNN_SMEM 137728

__device__ __forceinline__ void load_tile_hi(char* sm, uint32_t ohi, int node0, int tid) {
    const uint4* HI = (const uint4*)g_hi;
    #pragma unroll
    for (int it = 0; it < 8; ++it) {
        int idx = tid + it*256;
        int row = idx >> 4;
        int c8  = idx & 15;
        uint32_t so = (uint32_t)(row*SSTR + c8*8)*2;
        size_t gi = ((size_t)(node0 + row)*HDIM + c8*8) >> 3;
        *(uint4*)(sm + ohi + so) = HI[gi];
    }
}

__global__ void __launch_bounds__(256) k_knn_mma() {
    extern __shared__ char sm[];
    const uint32_t smb = smem_u32(sm);
    const int tid = threadIdx.x, wid = tid >> 5, lane = tid & 31;
    const int wm = wid >> 1, wn = wid & 1;
    const int q0 = blockIdx.x * 128;
    const int c0 = blockIdx.y * CPS;

    load_tile_hi(sm, SM_AH, q0, tid);

    float td[QKEEP]; int ti[QKEEP];
    #pragma unroll
    for (int j = 0; j < QKEEP; j++) { td[j] = 3.0e38f; ti[j] = 0; }

    const uint32_t a_off = (uint32_t)((32*wm + (lane & 15))*SSTR + (lane >> 4)*8) * 2;
    const uint32_t b_off = (uint32_t)((64*wn + (lane >> 4)*8 + (lane & 7))*SSTR
                                      + ((lane >> 3) & 1)*8) * 2;
    float* dist = (float*)(sm + SM_DIST);
    float* snc  = (float*)(sm + SM_SNC);

    const int srow = tid >> 1;            // scan row (query within tile)
    const int shalf = (tid & 1) * 64;     // half-row base column

    for (int t = 0; t < TPC; ++t) {
        __syncthreads();
        load_tile_hi(sm, SM_BH, c0 + t*128, tid);
        if (tid < 128) snc[tid] = g_sn[c0 + t*128 + tid];
        __syncthreads();

        float acc[2][8][4];
        #pragma unroll
        for (int mf = 0; mf < 2; mf++)
            #pragma unroll
            for (int nf = 0; nf < 8; nf++)
                #pragma unroll
                for (int v = 0; v < 4; v++) acc[mf][nf][v] = 0.f;

        const uint32_t abase = smb + SM_AH + a_off;
        const uint32_t bbase = smb + SM_BH + b_off;
        #pragma unroll
        for (int ks = 0; ks < 8; ++ks) {
            uint32_t a0[4], a1[4];
            ldm_x4(a0, abase + ks*32);
            ldm_x4(a1, abase + ks*32 + 16*SSTR*2);
            #pragma unroll
            for (int nf = 0; nf < 4; ++nf) {
                uint32_t b[4];
                ldm_x4(b, bbase + ks*32 + nf*16*SSTR*2);
                mma16816(acc[0][nf*2],   a0, b);
                mma16816(acc[0][nf*2+1], a0, b + 2);
                mma16816(acc[1][nf*2],   a1, b);
                mma16816(acc[1][nf*2+1], a1, b + 2);
            }
        }

        {
            const int r0 = 32*wm + (lane >> 2);
            const int cb = 64*wn + (lane & 3)*2;
            #pragma unroll
            for (int mf = 0; mf < 2; mf++)
                #pragma unroll
                for (int nf = 0; nf < 8; nf++) {
                    float2 lo = { acc[mf][nf][0], acc[mf][nf][1] };
                    float2 hi = { acc[mf][nf][2], acc[mf][nf][3] };
                    *(float2*)&dist[(r0 + mf*16    )*132 + cb + nf*8] = lo;
                    *(float2*)&dist[(r0 + mf*16 + 8)*132 + cb + nf*8] = hi;
                }
        }
        __syncthreads();

        {
            const int cbase = c0 + t*128 + shalf;
            const float* dr = &dist[srow*132 + shalf];
            const float* sc = &snc[shalf];
            float worst = td[QKEEP-1];
            #pragma unroll 4
            for (int c = 0; c < 64; c++) {
                float d = sc[c] - 2.0f*dr[c];
                if (d < worst) { topk_insert<QKEEP>(td, ti, d, cbase + c); worst = td[QKEEP-1]; }
            }
        }
    }

    {
        int q = q0 + srow;
        int base = (q*KSPL + blockIdx.y)*2*QKEEP + (tid & 1)*QKEEP;
        #pragma unroll
        for (int j = 0; j < QKEEP; j++)
            g_pti[base + j] = ti[j];
    }
}

// ---------------- exact refine: fp32 distances on 64 survivors ----------------
__global__ void __launch_bounds__(256) k_refine(const float* __restrict__ X) {
    int wid = threadIdx.x >> 5, lane = threadIdx.x & 31;
    int q = blockIdx.x*8 + wid;
    float4 xi = *(const float4*)&X[(size_t)q*HDIM + lane*4];
    float dloc[2]; int iloc[2];
    dloc[0] = dloc[1] = 3.0e38f;
    iloc[0] = iloc[1] = 0x7fffffff;
    #pragma unroll 4
    for (int c = 0; c < KSPL*2*QKEEP; c++) {
        int j = g_pti[q*KSPL*2*QKEEP + c];
        float4 xj = *(const float4*)&X[(size_t)j*HDIM + lane*4];
        float p = xi.x*xj.x + xi.y*xj.y + xi.z*xj.z + xi.w*xj.w;
        #pragma unroll
        for (int o = 16; o; o >>= 1) p += __shfl_xor_sync(0xffffffffu, p, o);
        float d = g_sn[j] - 2.0f*p;    // sn_i constant per row: ranking-invariant
        if (lane == (c & 31)) { dloc[c >> 5] = d; iloc[c >> 5] = j; }
    }
    for (int r = 0; r < KNN; r++) {
        float d = dloc[0]; int idx = iloc[0]; int sl = 0;
        if (dloc[1] < d || (dloc[1] == d && iloc[1] < idx)) { d = dloc[1]; idx = iloc[1]; sl = 1; }
        float dw = d; int iw = idx;
        #pragma unroll
        for (int o = 16; o; o >>= 1) {
            float od = __shfl_xor_sync(0xffffffffu, dw, o);
            int   oi = __shfl_xor_sync(0xffffffffu, iw, o);
            if (od < dw || (od == dw && oi < iw)) { dw = od; iw = oi; }
        }
        if (d == dw && idx == iw) dloc[sl] = 3.0e38f;
        if (lane == 0) g_knn[q*KNN + r] = iw;
    }
}

// ---------------- fused EdgeConv MLP, HMMA bf16-split ----------------
#define ESTR1    72
#define ESTR2    136
#define SM_A1H   0
#define SM_A1L   18432
#define SM_W2H   36864
#define SM_W2L   55296
#define SM_W3H   0
#define SM_W3L   34816
#define SM_A2H   73728
#define SM_A2L   108544
#define SM_JIDX  143360
#define EDGE_SMEM (143360 + 512)

__global__ void __launch_bounds__(256) k_edge(
        const float* __restrict__ R, const float* __restrict__ S,
        const float* __restrict__ w2, const float* __restrict__ b2,
        const float* __restrict__ w3, const float* __restrict__ b3,
        float* __restrict__ E)
{
    extern __shared__ char sm[];
    const uint32_t smb = smem_u32(sm);
    const int tid = threadIdx.x, wid = tid >> 5, lane = tid & 31;
    const int wm = wid >> 1, wn = wid & 1;
    const int r0 = blockIdx.x * 128;
    int* jidx = (int*)(sm + SM_JIDX);

    if (tid < 128) jidx[tid] = g_knn[r0 + tid];

    {
        __nv_bfloat16* W2H = (__nv_bfloat16*)(sm + SM_W2H);
        __nv_bfloat16* W2L = (__nv_bfloat16*)(sm + SM_W2L);
        #pragma unroll
        for (int i = 0; i < 32; i++) {
            int e = tid + i*256;
            int k = e >> 7, n = e & 127;
            float v = w2[e];
            __nv_bfloat16 h = __float2bfloat16(v);
            W2H[n*ESTR1 + k] = h;
            W2L[n*ESTR1 + k] = __float2bfloat16(v - __bfloat162float(h));
        }
    }
    __syncthreads();

    {
        __nv_bfloat16* A1H = (__nv_bfloat16*)(sm + SM_A1H);
        __nv_bfloat16* A1L = (__nv_bfloat16*)(sm + SM_A1L);
        int row = tid >> 1;
        int cb = (tid & 1) * 32;
        int i = (r0 + row) >> 4;
        int j = jidx[row];
        const float* Ri = &R[(size_t)i*64 + cb];
        const float* Sj = &S[(size_t)j*64 + cb];
        #pragma unroll
        for (int c = 0; c < 32; c += 4) {
            float4 rv = *(const float4*)(Ri + c);
            float4 sv = *(const float4*)(Sj + c);
            float h0 = fmaxf(rv.x + sv.x, 0.f), h1 = fmaxf(rv.y + sv.y, 0.f);
            float h2 = fmaxf(rv.z + sv.z, 0.f), h3 = fmaxf(rv.w + sv.w, 0.f);
            __nv_bfloat162 a01 = split_hi2(h0, h1), a23 = split_hi2(h2, h3);
            *(__nv_bfloat162*)&A1H[row*ESTR1 + cb + c]     = a01;
            *(__nv_bfloat162*)&A1H[row*ESTR1 + cb + c + 2] = a23;
            *(__nv_bfloat162*)&A1L[row*ESTR1 + cb + c]     = split_lo2(h0, h1, a01);
            *(__nv_bfloat162*)&A1L[row*ESTR1 + cb + c + 2] = split_lo2(h2, h3, a23);
        }
    }
    __syncthreads();

    const uint32_t a_off2 = (uint32_t)((32*wm + (lane & 15))*ESTR1 + (lane >> 4)*8) * 2;
    const uint32_t b_off2 = (uint32_t)((64*wn + (lane >> 4)*8 + (lane & 7))*ESTR1
                                       + ((lane >> 3) & 1)*8) * 2;

    float acc[2][8][4];
    #pragma unroll
    for (int mf = 0; mf < 2; mf++)
        #pragma unroll
        for (int nf = 0; nf < 8; nf++)
            #pragma unroll
            for (int v = 0; v < 4; v++) acc[mf][nf][v] = 0.f;

    #pragma unroll
    for (int term = 0; term < 3; ++term) {
        const uint32_t abase = smb + (term == 2 ? SM_A1L : SM_A1H) + a_off2;
        const uint32_t bbase = smb + (term == 1 ? SM_W2L : SM_W2H) + b_off2;
        #pragma unroll
        for (int ks = 0; ks < 4; ++ks) {
            uint32_t a0[4], a1[4];
            ldm_x4(a0, abase + ks*32);
            ldm_x4(a1, abase + ks*32 + 16*ESTR1*2);
            #pragma unroll
            for (int nf = 0; nf < 4; ++nf) {
                uint32_t b[4];
                ldm_x4(b, bbase + ks*32 + nf*16*ESTR1*2);
                mma16816(acc[0][nf*2],   a0, b);
                mma16816(acc[0][nf*2+1], a0, b + 2);
                mma16816(acc[1][nf*2],   a1, b);
                mma16816(acc[1][nf*2+1], a1, b + 2);
            }
        }
    }
    __syncthreads();

    {
        __nv_bfloat16* A2H = (__nv_bfloat16*)(sm + SM_A2H);
        __nv_bfloat16* A2L = (__nv_bfloat16*)(sm + SM_A2L);
        const int re = 32*wm + (lane >> 2);
        const int ce = 64*wn + (lane & 3)*2;
        #pragma unroll
        for (int mf = 0; mf < 2; mf++)
            #pragma unroll
            for (int nf = 0; nf < 8; nf++) {
                int r = re + mf*16;
                int c = ce + nf*8;
                float v0 = fmaxf(acc[mf][nf][0] + b2[c],   0.f);
                float v1 = fmaxf(acc[mf][nf][1] + b2[c+1], 0.f);
                float v2 = fmaxf(acc[mf][nf][2] + b2[c],   0.f);
                float v3 = fmaxf(acc[mf][nf][3] + b2[c+1], 0.f);
                __nv_bfloat162 h01 = split_hi2(v0, v1), h23 = split_hi2(v2, v3);
                *(__nv_bfloat162*)&A2H[r*ESTR2 + c]       = h01;
                *(__nv_bfloat162*)&A2L[r*ESTR2 + c]       = split_lo2(v0, v1, h01);
                *(__nv_bfloat162*)&A2H[(r+8)*ESTR2 + c]   = h23;
                *(__nv_bfloat162*)&A2L[(r+8)*ESTR2 + c]   = split_lo2(v2, v3, h23);
            }
    }
    {
        __nv_bfloat16* W3H = (__nv_bfloat16*)(sm + SM_W3H);
        __nv_bfloat16* W3L = (__nv_bfloat16*)(sm + SM_W3L);
        #pragma unroll
        for (int i = 0; i < 64; i++) {
            int e = tid + i*256;
            int k = e >> 7, n = e & 127;
            float v = w3[e];
            __nv_bfloat16 h = __float2bfloat16(v);
            W3H[n*ESTR2 + k] = h;
            W3L[n*ESTR2 + k] = __float2bfloat16(v - __bfloat162float(h));
        }
    }
    __syncthreads();

    #pragma unroll
    for (int mf = 0; mf < 2; mf++)
        #pragma unroll
        for (int nf = 0; nf < 8; nf++)
            #pragma unroll
            for (int v = 0; v < 4; v++) acc[mf][nf][v] = 0.f;

    const uint32_t a_off3 = (uint32_t)((32*wm + (lane & 15))*ESTR2 + (lane >> 4)*8) * 2;
    const uint32_t b_off3 = (uint32_t)((64*wn + (lane >> 4)*8 + (lane & 7))*ESTR2
                                       + ((lane >> 3) & 1)*8) * 2;
    #pragma unroll
    for (int term = 0; term < 3; ++term) {
        const uint32_t abase = smb + (term == 2 ? SM_A2L : SM_A2H) + a_off3;
        const uint32_t bbase = smb + (term == 1 ? SM_W3L : SM_W3H) + b_off3;
        #pragma unroll
        for (int ks = 0; ks < 8; ++ks) {
            uint32_t a0[4], a1[4];
            ldm_x4(a0, abase + ks*32);
            ldm_x4(a1, abase + ks*32 + 16*ESTR2*2);
            #pragma unroll
            for (int nf = 0; nf < 4; ++nf) {
                uint32_t b[4];
                ldm_x4(b, bbase + ks*32 + nf*16*ESTR2*2);
                mma16816(acc[0][nf*2],   a0, b);
                mma16816(acc[0][nf*2+1], a0, b + 2);
                mma16816(acc[1][nf*2],   a1, b);
                mma16816(acc[1][nf*2+1], a1, b + 2);
            }
        }
    }

    {
        const int ce = 64*wn + (lane & 3)*2;
        #pragma unroll
        for (int mf = 0; mf < 2; mf++) {
            int node = blockIdx.x*8 + 2*wm + mf;
            #pragma unroll
            for (int nf = 0; nf < 8; nf++) {
                float v0 = fmaxf(acc[mf][nf][0], acc[mf][nf][2]);
                float v1 = fmaxf(acc[mf][nf][1], acc[mf][nf][3]);
                #pragma unroll
                for (int o = 4; o < 32; o <<= 1) {
                    v0 = fmaxf(v0, __shfl_xor_sync(0xffffffffu, v0, o));
                    v1 = fmaxf(v1, __shfl_xor_sync(0xffffffffu, v1, o));
                }
                if ((lane >> 2) == 0) {
                    int c = ce + nf*8;
                    E[(size_t)node*128 + c]     = v0 + b3[c];
                    E[(size_t)node*128 + c + 1] = v1 + b3[c+1];
                }
            }
        }
    }
}

// ---------------- SIMT SGEMM (GCN + R/S precompute) ----------------
template<int BN, int TN, int EPI>
__global__ __launch_bounds__(256) void k_gemm(const float* __restrict__ A,
        const float* __restrict__ B, const float* __restrict__ bias,
        float* __restrict__ C, int Kd)
{
    constexpr int BM = 128, BK = 16, TM = 8;
    __shared__ float As[BK][BM + 4];
    __shared__ float Bs[BK][BN + 4];
    const int tid = threadIdx.x;
    const int tx = tid & 15, ty = tid >> 4;
    const int r0 = blockIdx.x * BM;

    float acc[TM][TN];
    #pragma unroll
    for (int m = 0; m < TM; m++)
        #pragma unroll
        for (int n = 0; n < TN; n++) acc[m][n] = 0.f;

    for (int kb = 0; kb < Kd; kb += BK) {
        #pragma unroll
        for (int i = 0; i < 2; i++) {
            int f = tid + i*256;
            int r = f >> 2, c4 = f & 3;
            float4 v = *(const float4*)&A[(size_t)(r0 + r)*Kd + kb + c4*4];
            As[c4*4+0][r] = v.x; As[c4*4+1][r] = v.y;
            As[c4*4+2][r] = v.z; As[c4*4+3][r] = v.w;
        }
        constexpr int BF4 = BK*BN/4;
        #pragma unroll
        for (int i = 0; i < BF4/256; i++) {
            int f = tid + i*256;
            int r = f / (BN/4), c4 = f % (BN/4);
            *(float4*)&Bs[r][c4*4] = *(const float4*)&B[(size_t)(kb + r)*BN + c4*4];
        }
        __syncthreads();
        #pragma unroll
        for (int kk = 0; kk < BK; kk++) {
            float a[TM], b[TN];
            *(float4*)&a[0] = *(const float4*)&As[kk][ty*TM];
            *(float4*)&a[4] = *(const float4*)&As[kk][ty*TM + 4];
            #pragma unroll
            for (int n = 0; n < TN; n += 4)
                *(float4*)&b[n] = *(const float4*)&Bs[kk][tx*TN + n];
            #pragma unroll
            for (int m = 0; m < TM; m++)
                #pragma unroll
                for (int n = 0; n < TN; n++) acc[m][n] += a[m] * b[n];
        }
        __syncthreads();
    }

    #pragma unroll
    for (int m = 0; m < TM; m++) {
        size_t r = r0 + ty*TM + m;
        #pragma unroll
        for (int n = 0; n < TN; n += 4) {
            float4 v;
            v.x = acc[m][n]; v.y = acc[m][n+1]; v.z = acc[m][n+2]; v.w = acc[m][n+3];
            if constexpr (EPI == 1 || EPI == 3) {
                int c = tx*TN + n;
                v.x += bias[c]; v.y += bias[c+1]; v.z += bias[c+2]; v.w += bias[c+3];
                if constexpr (EPI == 1) {
                    v.x = fmaxf(v.x, 0.f); v.y = fmaxf(v.y, 0.f);
                    v.z = fmaxf(v.z, 0.f); v.w = fmaxf(v.w, 0.f);
                }
            }
            *(float4*)&C[r*BN + tx*TN + n] = v;
        }
    }
}

// ---------------- epilogue kernels ----------------
__global__ void k_rownorm() {
    int w = threadIdx.x >> 5, lane = threadIdx.x & 31;
    int i = blockIdx.x*8 + w;
    float4 e = *(const float4*)&g_e[0][i*HDIM + lane*4];
    float4 n = *(const float4*)&g_nbuf[0][i*HDIM + lane*4];
    float a = e.x + n.x, b = e.y + n.y, c = e.z + n.z, d = e.w + n.w;
    float s = a*a + b*b + c*c + d*d;
    #pragma unroll
    for (int o = 16; o; o >>= 1) s += __shfl_xor_sync(0xffffffffu, s, o);
    if (lane == 0) g_r1[i] = sqrtf(s);
}

__global__ void k_final(float* __restrict__ out) {
    int w = threadIdx.x >> 5, lane = threadIdx.x & 31;
    int i = blockIdx.x*8 + w;
    float r = g_r1[i];
    float4 e2 = *(const float4*)&g_e[1][i*HDIM + lane*4];
    float4 n2 = *(const float4*)&g_nbuf[1][i*HDIM + lane*4];
    float4 e3 = *(const float4*)&g_e[2][i*HDIM + lane*4];
    float4 n3 = *(const float4*)&g_nbuf[2][i*HDIM + lane*4];
    float v0 = r * (e2.x + n2.x) * (e3.x + n3.x);
    float v1 = r * (e2.y + n2.y) * (e3.y + n3.y);
    float v2 = r * (e2.z + n2.z) * (e3.z + n3.z);
    float v3 = r * (e2.w + n2.w) * (e3.w + n3.w);
    float m = fmaxf(fmaxf(v0, v1), fmaxf(v2, v3));
    #pragma unroll
    for (int o = 16; o; o >>= 1) m = fmaxf(m, __shfl_xor_sync(0xffffffffu, m, o));
    float s = expf(v0 - m) + expf(v1 - m) + expf(v2 - m) + expf(v3 - m);
    #pragma unroll
    for (int o = 16; o; o >>= 1) s += __shfl_xor_sync(0xffffffffu, s, o);
    float lse = m + logf(s);
    float4 ov = { v0 - lse, v1 - lse, v2 - lse, v3 - lse };
    *(float4*)&out[i*HDIM + lane*4] = ov;
}

// ---------------- launch ----------------
extern "C" void kernel_launch(void* const* d_in, const int* in_sizes, int n_in,
                              void* d_out, int out_size) {
    const float* x  = (const float*)d_in[0];
    const int*   ei = (const int*)  d_in[1];
    const float* ew = (const float*)d_in[2];
    const float* wg[3] = {(const float*)d_in[3], (const float*)d_in[5], (const float*)d_in[7]};
    const float* bg[3] = {(const float*)d_in[4], (const float*)d_in[6], (const float*)d_in[8]};

    float *p_h, *p_n, *p_e, *p_R, *p_S, *p_wd;
    cudaGetSymbolAddress((void**)&p_h,  g_h);
    cudaGetSymbolAddress((void**)&p_n,  g_nbuf);
    cudaGetSymbolAddress((void**)&p_e,  g_e);
    cudaGetSymbolAddress((void**)&p_R,  g_R);
    cudaGetSymbolAddress((void**)&p_S,  g_S);
    cudaGetSymbolAddress((void**)&p_wd, g_wd);

    cudaFuncSetAttribute(k_knn_mma, cudaFuncAttributeMaxDynamicSharedMemorySize, KNN_SMEM);
    cudaFuncSetAttribute(k_edge,    cudaFuncAttributeMaxDynamicSharedMemorySize, EDGE_SMEM);

    // graph prep (once)
    k_deg_init<<<NNODES/256, 256>>>();
    k_deg<<<NEDGE/256, 256>>>(ei, ew);
    k_dis<<<NNODES/256, 256>>>();
    k_scan<<<1, 1024>>>();
    k_place<<<NEDGE/256, 256>>>(ei, ew);

    const float* cur = x;
    for (int L = 0; L < 3; L++) {
        float* nL = p_n + (size_t)L * NNODES * HDIM;
        float* eL = p_e + (size_t)L * NNODES * HDIM;
        const float* w1 = (const float*)d_in[9 + L*6 + 0];
        const float* b1 = (const float*)d_in[9 + L*6 + 1];
        const float* w2 = (const float*)d_in[9 + L*6 + 2];
        const float* b2 = (const float*)d_in[9 + L*6 + 3];
        const float* w3 = (const float*)d_in[9 + L*6 + 4];
        const float* b3 = (const float*)d_in[9 + L*6 + 5];

        // GCN
        k_gemm<128,8,0><<<NNODES/128, 256>>>(cur, wg[L], nullptr, p_h, 128);
        k_gather<<<NNODES/8, 256>>>(bg[L], nL);

        // kNN: approx bf16 filter (quarter-scan) + exact fp32 refine
        k_knn_mma<<<dim3(NNODES/128, KSPL), 256, KNN_SMEM>>>();
        k_refine<<<NNODES/8, 256>>>(nL);

        // EdgeConv
        k_wdiff<<<8192/256, 256>>>(w1);
        k_gemm<64,4,3><<<NNODES/128, 256>>>(nL, p_wd,        b1,      p_R, 128);
        k_gemm<64,4,0><<<NNODES/128, 256>>>(nL, w1 + 128*64, nullptr, p_S, 128);
        k_edge<<<NKR/128, 256, EDGE_SMEM>>>(p_R, p_S, w2, b2, w3, b3, eL);

        cur = nL;
    }

    k_rownorm<<<NNODES/8, 256>>>();
    k_final<<<NNODES/8, 256>>>((float*)d_out);
}

// round 11
// speedup vs baseline: 1.4044x; 1.0056x over previous
#include <cuda_runtime.h>
#include <cuda_bf16.h>
#include <math.h>
#include <stdint.h>

#define NNODES 8192
#define HDIM   128
#define KNN    16
#define NEDGE  262144
#define NKR    (NNODES*KNN)
#define KSPL   2
#define CPS    (NNODES/KSPL)
#define TPC    (CPS/128)
#define QKEEP  16

// ---------------- scratch (device globals) ----------------
static __device__ float g_h[NNODES*HDIM];
static __device__ float g_nbuf[3][NNODES*HDIM];
static __device__ float g_sn[NNODES];
static __device__ float g_deg[NNODES];
static __device__ float g_dis[NNODES];
static __device__ int   g_knn[NKR];
static __device__ float g_e[3][NNODES*HDIM];
static __device__ int   g_pti[KSPL*NNODES*2*QKEEP];
static __device__ __nv_bfloat16 g_hi[NNODES*HDIM];
static __device__ __nv_bfloat16 g_lo[NNODES*HDIM];
static __device__ float g_RS[NNODES*128];
static __device__ float g_wc[128*128];
static __device__ float g_bc[128];
// CSR
static __device__ int   g_cnt[NNODES];
static __device__ int   g_off[NNODES+1];
static __device__ int   g_cur[NNODES];
static __device__ int   g_esrc[NEDGE];
static __device__ float g_enrm[NEDGE];

// ---------------- helpers ----------------
__device__ __forceinline__ uint32_t smem_u32(const void* p) {
    uint32_t a;
    asm("{ .reg .u64 t; cvta.to.shared.u64 t, %1; cvt.u32.u64 %0, t; }" : "=r"(a) : "l"(p));
    return a;
}
__device__ __forceinline__ void ldm_x4(uint32_t* r, uint32_t addr) {
    asm volatile("ldmatrix.sync.aligned.m8n8.x4.shared.b16 {%0,%1,%2,%3}, [%4];"
        : "=r"(r[0]), "=r"(r[1]), "=r"(r[2]), "=r"(r[3]) : "r"(addr));
}
__device__ __forceinline__ void mma16816(float* c, const uint32_t* a, const uint32_t* b) {
    asm volatile("mma.sync.aligned.m16n8k16.row.col.f32.bf16.bf16.f32 "
        "{%0,%1,%2,%3}, {%4,%5,%6,%7}, {%8,%9}, {%0,%1,%2,%3};"
        : "+f"(c[0]), "+f"(c[1]), "+f"(c[2]), "+f"(c[3])
        : "r"(a[0]), "r"(a[1]), "r"(a[2]), "r"(a[3]), "r"(b[0]), "r"(b[1]));
}
__device__ __forceinline__ __nv_bfloat162 split_hi2(float a, float b) {
    __nv_bfloat162 r; r.x = __float2bfloat16(a); r.y = __float2bfloat16(b); return r;
}
__device__ __forceinline__ __nv_bfloat162 split_lo2(float a, float b, __nv_bfloat162 h) {
    __nv_bfloat162 r;
    r.x = __float2bfloat16(a - __bfloat162float(h.x));
    r.y = __float2bfloat16(b - __bfloat162float(h.y));
    return r;
}

// ---------------- graph prep ----------------
__global__ void k_deg_init() {
    int i = blockIdx.x*blockDim.x + threadIdx.x;
    if (i < NNODES) { g_deg[i] = 1.0f; g_cnt[i] = 0; }
}
__global__ void k_deg(const int* __restrict__ ei, const float* __restrict__ ew) {
    int e = blockIdx.x*blockDim.x + threadIdx.x;
    if (e < NEDGE) {
        atomicAdd(&g_deg[ei[NEDGE + e]], ew[e]);
        atomicAdd(&g_cnt[ei[NEDGE + e]], 1);
    }
}
__global__ void k_dis() {
    int i = blockIdx.x*blockDim.x + threadIdx.x;
    if (i < NNODES) g_dis[i] = rsqrtf(g_deg[i]);
}
__global__ void k_scan() {
    __shared__ int ws[32];
    int t = threadIdx.x, lane = t & 31, w = t >> 5;
    int base = t*8;
    int v[8], s = 0;
    #pragma unroll
    for (int i = 0; i < 8; i++) { v[i] = s; s += g_cnt[base + i]; }
    int x = s;
    #pragma unroll
    for (int o = 1; o < 32; o <<= 1) {
        int y = __shfl_up_sync(0xffffffffu, x, o);
        if (lane >= o) x += y;
    }
    if (lane == 31) ws[w] = x;
    __syncthreads();
    if (w == 0) {
        int y = ws[lane];
        #pragma unroll
        for (int o = 1; o < 32; o <<= 1) {
            int z = __shfl_up_sync(0xffffffffu, y, o);
            if (lane >= o) y += z;
        }
        ws[lane] = y;
    }
    __syncthreads();
    int off = x - s + (w ? ws[w-1] : 0);
    #pragma unroll
    for (int i = 0; i < 8; i++) { g_off[base + i] = off + v[i]; g_cur[base + i] = off + v[i]; }
    if (t == 1023) g_off[NNODES] = off + s;
}
__global__ void k_place(const int* __restrict__ ei, const float* __restrict__ ew) {
    int e = blockIdx.x*blockDim.x + threadIdx.x;
    if (e < NEDGE) {
        int s = ei[e], d = ei[NEDGE + e];
        int slot = atomicAdd(&g_cur[d], 1);
        g_esrc[slot] = s;
        g_enrm[slot] = g_dis[s] * ew[e] * g_dis[d];
    }
}

// ---------------- fused GCN aggregate + tanh + sn + split (4-wide MLP) ----------------
__global__ void __launch_bounds__(256) k_gather(const float* __restrict__ bg,
                                                float* __restrict__ out) {
    int wid = threadIdx.x >> 5, lane = threadIdx.x & 31;
    int node = blockIdx.x*8 + wid;
    int c = lane*4;
    float dsq = g_dis[node]; dsq *= dsq;
    float4 v = *(const float4*)&g_h[node*HDIM + c];
    v.x *= dsq; v.y *= dsq; v.z *= dsq; v.w *= dsq;
    int beg = g_off[node], end = g_off[node+1];
    int p = beg;
    for (; p + 3 < end; p += 4) {
        int s0 = g_esrc[p], s1 = g_esrc[p+1], s2 = g_esrc[p+2], s3 = g_esrc[p+3];
        float n0 = g_enrm[p], n1 = g_enrm[p+1], n2 = g_enrm[p+2], n3 = g_enrm[p+3];
        float4 h0 = *(const float4*)&g_h[s0*HDIM + c];
        float4 h1 = *(const float4*)&g_h[s1*HDIM + c];
        float4 h2 = *(const float4*)&g_h[s2*HDIM + c];
        float4 h3 = *(const float4*)&g_h[s3*HDIM + c];
        v.x += n0*h0.x + n1*h1.x + n2*h2.x + n3*h3.x;
        v.y += n0*h0.y + n1*h1.y + n2*h2.y + n3*h3.y;
        v.z += n0*h0.z + n1*h1.z + n2*h2.z + n3*h3.z;
        v.w += n0*h0.w + n1*h1.w + n2*h2.w + n3*h3.w;
    }
    for (; p < end; ++p) {
        int s = g_esrc[p];
        float nr = g_enrm[p];
        float4 hv = *(const float4*)&g_h[s*HDIM + c];
        v.x += nr*hv.x; v.y += nr*hv.y; v.z += nr*hv.z; v.w += nr*hv.w;
    }
    float4 b = *(const float4*)&bg[c];
    float t0 = tanhf(v.x + b.x), t1 = tanhf(v.y + b.y);
    float t2 = tanhf(v.z + b.z), t3 = tanhf(v.w + b.w);
    *(float4*)&out[node*HDIM + c] = make_float4(t0, t1, t2, t3);
    float ss = t0*t0 + t1*t1 + t2*t2 + t3*t3;
    #pragma unroll
    for (int o = 16; o; o >>= 1) ss += __shfl_xor_sync(0xffffffffu, ss, o);
    if (lane == 0) g_sn[node] = ss;
    __nv_bfloat162 h01 = split_hi2(t0, t1), h23 = split_hi2(t2, t3);
    __nv_bfloat162 l01 = split_lo2(t0, t1, h01), l23 = split_lo2(t2, t3, h23);
    *(__nv_bfloat162*)&g_hi[node*HDIM + c]     = h01;
    *(__nv_bfloat162*)&g_hi[node*HDIM + c + 2] = h23;
    *(__nv_bfloat162*)&g_lo[node*HDIM + c]     = l01;
    *(__nv_bfloat162*)&g_lo[node*HDIM + c + 2] = l23;
}

// ---------------- combined W1 build: g_wc = [W1a - W1b | W1b], g_bc = [b1 | 0] ----------------
__global__ void k_wcomb(const float* __restrict__ w1, const float* __restrict__ b1) {
    int i = blockIdx.x*blockDim.x + threadIdx.x;   // 16384
    int k = i >> 7, n = i & 127;
    float v = (n < 64) ? (w1[k*64 + n] - w1[(k + 128)*64 + n])
                       : w1[(k + 128)*64 + (n - 64)];
    g_wc[i] = v;
    if (i < 128) g_bc[i] = (i < 64) ? b1[i] : 0.f;
}

// ---------------- top-K insertion ----------------
template<int NK>
__device__ __forceinline__ void topk_insert(float (&td)[NK], int (&ti)[NK], float d, int idx) {
    if (d >= td[NK-1]) return;
    #pragma unroll
    for (int p = NK-1; p > 0; --p) {
        bool sh = td[p-1] > d;
        float nd = sh ? td[p-1] : d;
        int   ni = sh ? ti[p-1] : idx;
        if (td[p] > d) { td[p] = nd; ti[p] = ni; }
    }
    if (td[0] > d) { td[0] = d; ti[0] = idx; }
}

// ---------------- approx kNN ----------------
#define SSTR    136
#define SM_AH   0
#define SM_BH   34816
#define SM_DIST 69632
#define SM_SNC  137216
#define KNN_SMEM 137728

__device__ __forceinline__ void load_tile_hi(char* sm, uint32_t ohi, int node0, int tid) {
    const uint4* HI = (const uint4*)g_hi;
    #pragma unroll
    for (int it = 0; it < 8; ++it) {
        int idx = tid + it*256;
        int row = idx >> 4;
        int c8  = idx & 15;
        uint32_t so = (uint32_t)(row*SSTR + c8*8)*2;
        size_t gi = ((size_t)(node0 + row)*HDIM + c8*8) >> 3;
        *(uint4*)(sm + ohi + so) = HI[gi];
    }
}

__global__ void __launch_bounds__(256) k_knn_mma() {
    extern __shared__ char sm[];
    const uint32_t smb = smem_u32(sm);
    const int tid = threadIdx.x, wid = tid >> 5, lane = tid & 31;
    const int wm = wid >> 1, wn = wid & 1;
    const int q0 = blockIdx.x * 128;
    const int c0 = blockIdx.y * CPS;

    load_tile_hi(sm, SM_AH, q0, tid);

    float td[QKEEP]; int ti[QKEEP];
    #pragma unroll
    for (int j = 0; j < QKEEP; j++) { td[j] = 3.0e38f; ti[j] = 0; }

    const uint32_t a_off = (uint32_t)((32*wm + (lane & 15))*SSTR + (lane >> 4)*8) * 2;
    const uint32_t b_off = (uint32_t)((64*wn + (lane >> 4)*8 + (lane & 7))*SSTR
                                      + ((lane >> 3) & 1)*8) * 2;
    float* dist = (float*)(sm + SM_DIST);
    float* snc  = (float*)(sm + SM_SNC);

    const int srow = tid >> 1;
    const int shalf = (tid & 1) * 64;

    for (int t = 0; t < TPC; ++t) {
        __syncthreads();
        load_tile_hi(sm, SM_BH, c0 + t*128, tid);
        if (tid < 128) snc[tid] = g_sn[c0 + t*128 + tid];
        __syncthreads();

        float acc[2][8][4];
        #pragma unroll
        for (int mf = 0; mf < 2; mf++)
            #pragma unroll
            for (int nf = 0; nf < 8; nf++)
                #pragma unroll
                for (int v = 0; v < 4; v++) acc[mf][nf][v] = 0.f;

        const uint32_t abase = smb + SM_AH + a_off;
        const uint32_t bbase = smb + SM_BH + b_off;
        #pragma unroll
        for (int ks = 0; ks < 8; ++ks) {
            uint32_t a0[4], a1[4];
            ldm_x4(a0, abase + ks*32);
            ldm_x4(a1, abase + ks*32 + 16*SSTR*2);
            #pragma unroll
            for (int nf = 0; nf < 4; ++nf) {
                uint32_t b[4];
                ldm_x4(b, bbase + ks*32 + nf*16*SSTR*2);
                mma16816(acc[0][nf*2],   a0, b);
                mma16816(acc[0][nf*2+1], a0, b + 2);
                mma16816(acc[1][nf*2],   a1, b);
                mma16816(acc[1][nf*2+1], a1, b + 2);
            }
        }

        {
            const int r0 = 32*wm + (lane >> 2);
            const int cb = 64*wn + (lane & 3)*2;
            #pragma unroll
            for (int mf = 0; mf < 2; mf++)
                #pragma unroll
                for (int nf = 0; nf < 8; nf++) {
                    float2 lo = { acc[mf][nf][0], acc[mf][nf][1] };
                    float2 hi = { acc[mf][nf][2], acc[mf][nf][3] };
                    *(float2*)&dist[(r0 + mf*16    )*132 + cb + nf*8] = lo;
                    *(float2*)&dist[(r0 + mf*16 + 8)*132 + cb + nf*8] = hi;
                }
        }
        __syncthreads();

        {
            const int cbase = c0 + t*128 + shalf;
            const float* dr = &dist[srow*132 + shalf];
            const float* sc = &snc[shalf];
            float worst = td[QKEEP-1];
            #pragma unroll 4
            for (int c = 0; c < 64; c++) {
                float d = sc[c] - 2.0f*dr[c];
                if (d < worst) { topk_insert<QKEEP>(td, ti, d, cbase + c); worst = td[QKEEP-1]; }
            }
        }
    }

    {
        int q = q0 + srow;
        int base = (q*KSPL + blockIdx.y)*2*QKEEP + (tid & 1)*QKEEP;
        #pragma unroll
        for (int j = 0; j < QKEEP; j++)
            g_pti[base + j] = ti[j];
    }
}

// ---------------- exact refine ----------------
__global__ void __launch_bounds__(256) k_refine(const float* __restrict__ X) {
    int wid = threadIdx.x >> 5, lane = threadIdx.x & 31;
    int q = blockIdx.x*8 + wid;
    float4 xi = *(const float4*)&X[(size_t)q*HDIM + lane*4];
    float dloc[2]; int iloc[2];
    dloc[0] = dloc[1] = 3.0e38f;
    iloc[0] = iloc[1] = 0x7fffffff;
    #pragma unroll 4
    for (int c = 0; c < KSPL*2*QKEEP; c++) {
        int j = g_pti[q*KSPL*2*QKEEP + c];
        float4 xj = *(const float4*)&X[(size_t)j*HDIM + lane*4];
        float p = xi.x*xj.x + xi.y*xj.y + xi.z*xj.z + xi.w*xj.w;
        #pragma unroll
        for (int o = 16; o; o >>= 1) p += __shfl_xor_sync(0xffffffffu, p, o);
        float d = g_sn[j] - 2.0f*p;
        if (lane == (c & 31)) { dloc[c >> 5] = d; iloc[c >> 5] = j; }
    }
    for (int r = 0; r < KNN; r++) {
        float d = dloc[0]; int idx = iloc[0]; int sl = 0;
        if (dloc[1] < d || (dloc[1] == d && iloc[1] < idx)) { d = dloc[1]; idx = iloc[1]; sl = 1; }
        float dw = d; int iw = idx;
        #pragma unroll
        for (int o = 16; o; o >>= 1) {
            float od = __shfl_xor_sync(0xffffffffu, dw, o);
            int   oi = __shfl_xor_sync(0xffffffffu, iw, o);
            if (od < dw || (od == dw && oi < iw)) { dw = od; iw = oi; }
        }
        if (d == dw && idx == iw) dloc[sl] = 3.0e38f;
        if (lane == 0) g_knn[q*KNN + r] = iw;
    }
}

// ---------------- fused EdgeConv MLP, HMMA bf16-split (combined RS layout) ----------------
#define ESTR1    72
#define ESTR2    136
#define SM_A1H   0
#define SM_A1L   18432
#define SM_W2H   36864
#define SM_W2L   55296
#define SM_W3H   0
#define SM_W3L   34816
#define SM_A2H   73728
#define SM_A2L   108544
#define SM_JIDX  143360
#define EDGE_SMEM (143360 + 512)

__global__ void __launch_bounds__(256) k_edge(
        const float* __restrict__ RS,
        const float* __restrict__ w2, const float* __restrict__ b2,
        const float* __restrict__ w3, const float* __restrict__ b3,
        float* __restrict__ E)
{
    extern __shared__ char sm[];
    const uint32_t smb = smem_u32(sm);
    const int tid = threadIdx.x, wid = tid >> 5, lane = tid & 31;
    const int wm = wid >> 1, wn = wid & 1;
    const int r0 = blockIdx.x * 128;
    int* jidx = (int*)(sm + SM_JIDX);

    if (tid < 128) jidx[tid] = g_knn[r0 + tid];

    {
        __nv_bfloat16* W2H = (__nv_bfloat16*)(sm + SM_W2H);
        __nv_bfloat16* W2L = (__nv_bfloat16*)(sm + SM_W2L);
        #pragma unroll
        for (int i = 0; i < 32; i++) {
            int e = tid + i*256;
            int k = e >> 7, n = e & 127;
            float v = w2[e];
            __nv_bfloat16 h = __float2bfloat16(v);
            W2H[n*ESTR1 + k] = h;
            W2L[n*ESTR1 + k] = __float2bfloat16(v - __bfloat162float(h));
        }
    }
    __syncthreads();

    {
        __nv_bfloat16* A1H = (__nv_bfloat16*)(sm + SM_A1H);
        __nv_bfloat16* A1L = (__nv_bfloat16*)(sm + SM_A1L);
        int row = tid >> 1;
        int cb = (tid & 1) * 32;
        int i = (r0 + row) >> 4;
        int j = jidx[row];
        const float* Ri = &RS[(size_t)i*128 + cb];
        const float* Sj = &RS[(size_t)j*128 + 64 + cb];
        #pragma unroll
        for (int c = 0; c < 32; c += 4) {
            float4 rv = *(const float4*)(Ri + c);
            float4 sv = *(const float4*)(Sj + c);
            float h0 = fmaxf(rv.x + sv.x, 0.f), h1 = fmaxf(rv.y + sv.y, 0.f);
            float h2 = fmaxf(rv.z + sv.z, 0.f), h3 = fmaxf(rv.w + sv.w, 0.f);
            __nv_bfloat162 a01 = split_hi2(h0, h1), a23 = split_hi2(h2, h3);
            *(__nv_bfloat162*)&A1H[row*ESTR1 + cb + c]     = a01;
            *(__nv_bfloat162*)&A1H[row*ESTR1 + cb + c + 2] = a23;
            *(__nv_bfloat162*)&A1L[row*ESTR1 + cb + c]     = split_lo2(h0, h1, a01);
            *(__nv_bfloat162*)&A1L[row*ESTR1 + cb + c + 2] = split_lo2(h2, h3, a23);
        }
    }
    __syncthreads();

    const uint32_t a_off2 = (uint32_t)((32*wm + (lane & 15))*ESTR1 + (lane >> 4)*8) * 2;
    const uint32_t b_off2 = (uint32_t)((64*wn + (lane >> 4)*8 + (lane & 7))*ESTR1
                                       + ((lane >> 3) & 1)*8) * 2;

    float acc[2][8][4];
    #pragma unroll
    for (int mf = 0; mf < 2; mf++)
        #pragma unroll
        for (int nf = 0; nf < 8; nf++)
            #pragma unroll
            for (int v = 0; v < 4; v++) acc[mf][nf][v] = 0.f;

    #pragma unroll
    for (int term = 0; term < 3; ++term) {
        const uint32_t abase = smb + (term == 2 ? SM_A1L : SM_A1H) + a_off2;
        const uint32_t bbase = smb + (term == 1 ? SM_W2L : SM_W2H) + b_off2;
        #pragma unroll
        for (int ks = 0; ks < 4; ++ks) {
            uint32_t a0[4], a1[4];
            ldm_x4(a0, abase + ks*32);
            ldm_x4(a1, abase + ks*32 + 16*ESTR1*2);
            #pragma unroll
            for (int nf = 0; nf < 4; ++nf) {
                uint32_t b[4];
                ldm_x4(b, bbase + ks*32 + nf*16*ESTR1*2);
                mma16816(acc[0][nf*2],   a0, b);
                mma16816(acc[0][nf*2+1], a0, b + 2);
                mma16816(acc[1][nf*2],   a1, b);
                mma16816(acc[1][nf*2+1], a1, b + 2);
            }
        }
    }
    __syncthreads();

    {
        __nv_bfloat16* A2H = (__nv_bfloat16*)(sm + SM_A2H);
        __nv_bfloat16* A2L = (__nv_bfloat16*)(sm + SM_A2L);
        const int re = 32*wm + (lane >> 2);
        const int ce = 64*wn + (lane & 3)*2;
        #pragma unroll
        for (int mf = 0; mf < 2; mf++)
            #pragma unroll
            for (int nf = 0; nf < 8; nf++) {
                int r = re + mf*16;
                int c = ce + nf*8;
                float v0 = fmaxf(acc[mf][nf][0] + b2[c],   0.f);
                float v1 = fmaxf(acc[mf][nf][1] + b2[c+1], 0.f);
                float v2 = fmaxf(acc[mf][nf][2] + b2[c],   0.f);
                float v3 = fmaxf(acc[mf][nf][3] + b2[c+1], 0.f);
                __nv_bfloat162 h01 = split_hi2(v0, v1), h23 = split_hi2(v2, v3);
                *(__nv_bfloat162*)&A2H[r*ESTR2 + c]       = h01;
                *(__nv_bfloat162*)&A2L[r*ESTR2 + c]       = split_lo2(v0, v1, h01);
                *(__nv_bfloat162*)&A2H[(r+8)*ESTR2 + c]   = h23;
                *(__nv_bfloat162*)&A2L[(r+8)*ESTR2 + c]   = split_lo2(v2, v3, h23);
            }
    }
    {
        __nv_bfloat16* W3H = (__nv_bfloat16*)(sm + SM_W3H);
        __nv_bfloat16* W3L = (__nv_bfloat16*)(sm + SM_W3L);
        #pragma unroll
        for (int i = 0; i < 64; i++) {
            int e = tid + i*256;
            int k = e >> 7, n = e & 127;
            float v = w3[e];
            __nv_bfloat16 h = __float2bfloat16(v);
            W3H[n*ESTR2 + k] = h;
            W3L[n*ESTR2 + k] = __float2bfloat16(v - __bfloat162float(h));
        }
    }
    __syncthreads();

    #pragma unroll
    for (int mf = 0; mf < 2; mf++)
        #pragma unroll
        for (int nf = 0; nf < 8; nf++)
            #pragma unroll
            for (int v = 0; v < 4; v++) acc[mf][nf][v] = 0.f;

    const uint32_t a_off3 = (uint32_t)((32*wm + (lane & 15))*ESTR2 + (lane >> 4)*8) * 2;
    const uint32_t b_off3 = (uint32_t)((64*wn + (lane >> 4)*8 + (lane & 7))*ESTR2
                                       + ((lane >> 3) & 1)*8) * 2;
    #pragma unroll
    for (int term = 0; term < 3; ++term) {
        const uint32_t abase = smb + (term == 2 ? SM_A2L : SM_A2H) + a_off3;
        const uint32_t bbase = smb + (term == 1 ? SM_W3L : SM_W3H) + b_off3;
        #pragma unroll
        for (int ks = 0; ks < 8; ++ks) {
            uint32_t a0[4], a1[4];
            ldm_x4(a0, abase + ks*32);
            ldm_x4(a1, abase + ks*32 + 16*ESTR2*2);
            #pragma unroll
            for (int nf = 0; nf < 4; ++nf) {
                uint32_t b[4];
                ldm_x4(b, bbase + ks*32 + nf*16*ESTR2*2);
                mma16816(acc[0][nf*2],   a0, b);
                mma16816(acc[0][nf*2+1], a0, b + 2);
                mma16816(acc[1][nf*2],   a1, b);
                mma16816(acc[1][nf*2+1], a1, b + 2);
            }
        }
    }

    {
        const int ce = 64*wn + (lane & 3)*2;
        #pragma unroll
        for (int mf = 0; mf < 2; mf++) {
            int node = blockIdx.x*8 + 2*wm + mf;
            #pragma unroll
            for (int nf = 0; nf < 8; nf++) {
                float v0 = fmaxf(acc[mf][nf][0], acc[mf][nf][2]);
                float v1 = fmaxf(acc[mf][nf][1], acc[mf][nf][3]);
                #pragma unroll
                for (int o = 4; o < 32; o <<= 1) {
                    v0 = fmaxf(v0, __shfl_xor_sync(0xffffffffu, v0, o));
                    v1 = fmaxf(v1, __shfl_xor_sync(0xffffffffu, v1, o));
                }
                if ((lane >> 2) == 0) {
                    int c = ce + nf*8;
                    E[(size_t)node*128 + c]     = v0 + b3[c];
                    E[(size_t)node*128 + c + 1] = v1 + b3[c+1];
                }
            }
        }
    }
}

// ---------------- SIMT SGEMM (GCN + combined RS) ----------------
// EPI: 0 plain, 3 bias only
template<int BN, int TN, int EPI>
__global__ __launch_bounds__(256) void k_gemm(const float* __restrict__ A,
        const float* __restrict__ B, const float* __restrict__ bias,
        float* __restrict__ C, int Kd)
{
    constexpr int BM = 128, BK = 16, TM = 8;
    __shared__ float As[BK][BM + 4];
    __shared__ float Bs[BK][BN + 4];
    const int tid = threadIdx.x;
    const int tx = tid & 15, ty = tid >> 4;
    const int r0 = blockIdx.x * BM;

    float acc[TM][TN];
    #pragma unroll
    for (int m = 0; m < TM; m++)
        #pragma unroll
        for (int n = 0; n < TN; n++) acc[m][n] = 0.f;

    for (int kb = 0; kb < Kd; kb += BK) {
        #pragma unroll
        for (int i = 0; i < 2; i++) {
            int f = tid + i*256;
            int r = f >> 2, c4 = f & 3;
            float4 v = *(const float4*)&A[(size_t)(r0 + r)*Kd + kb + c4*4];
            As[c4*4+0][r] = v.x; As[c4*4+1][r] = v.y;
            As[c4*4+2][r] = v.z; As[c4*4+3][r] = v.w;
        }
        constexpr int BF4 = BK*BN/4;
        #pragma unroll
        for (int i = 0; i < BF4/256; i++) {
            int f = tid + i*256;
            int r = f / (BN/4), c4 = f % (BN/4);
            *(float4*)&Bs[r][c4*4] = *(const float4*)&B[(size_t)(kb + r)*BN + c4*4];
        }
        __syncthreads();
        #pragma unroll
        for (int kk = 0; kk < BK; kk++) {
            float a[TM], b[TN];
            *(float4*)&a[0] = *(const float4*)&As[kk][ty*TM];
            *(float4*)&a[4] = *(const float4*)&As[kk][ty*TM + 4];
            #pragma unroll
            for (int n = 0; n < TN; n += 4)
                *(float4*)&b[n] = *(const float4*)&Bs[kk][tx*TN + n];
            #pragma unroll
            for (int m = 0; m < TM; m++)
                #pragma unroll
                for (int n = 0; n < TN; n++) acc[m][n] += a[m] * b[n];
        }
        __syncthreads();
    }

    #pragma unroll
    for (int m = 0; m < TM; m++) {
        size_t r = r0 + ty*TM + m;
        #pragma unroll
        for (int n = 0; n < TN; n += 4) {
            float4 v;
            v.x = acc[m][n]; v.y = acc[m][n+1]; v.z = acc[m][n+2]; v.w = acc[m][n+3];
            if constexpr (EPI == 3) {
                int c = tx*TN + n;
                v.x += bias[c]; v.y += bias[c+1]; v.z += bias[c+2]; v.w += bias[c+3];
            }
            *(float4*)&C[r*BN + tx*TN + n] = v;
        }
    }
}

// ---------------- final: fused rownorm + product + log_softmax ----------------
__global__ void k_final(float* __restrict__ out) {
    int w = threadIdx.x >> 5, lane = threadIdx.x & 31;
    int i = blockIdx.x*8 + w;
    float4 e1 = *(const float4*)&g_e[0][i*HDIM + lane*4];
    float4 n1 = *(const float4*)&g_nbuf[0][i*HDIM + lane*4];
    float a = e1.x + n1.x, b = e1.y + n1.y, c = e1.z + n1.z, d = e1.w + n1.w;
    float s1 = a*a + b*b + c*c + d*d;
    #pragma unroll
    for (int o = 16; o; o >>= 1) s1 += __shfl_xor_sync(0xffffffffu, s1, o);
    float r = sqrtf(s1);

    float4 e2 = *(const float4*)&g_e[1][i*HDIM + lane*4];
    float4 n2 = *(const float4*)&g_nbuf[1][i*HDIM + lane*4];
    float4 e3 = *(const float4*)&g_e[2][i*HDIM + lane*4];
    float4 n3 = *(const float4*)&g_nbuf[2][i*HDIM + lane*4];
    float v0 = r * (e2.x + n2.x) * (e3.x + n3.x);
    float v1 = r * (e2.y + n2.y) * (e3.y + n3.y);
    float v2 = r * (e2.z + n2.z) * (e3.z + n3.z);
    float v3 = r * (e2.w + n2.w) * (e3.w + n3.w);
    float m = fmaxf(fmaxf(v0, v1), fmaxf(v2, v3));
    #pragma unroll
    for (int o = 16; o; o >>= 1) m = fmaxf(m, __shfl_xor_sync(0xffffffffu, m, o));
    float s = expf(v0 - m) + expf(v1 - m) + expf(v2 - m) + expf(v3 - m);
    #pragma unroll
    for (int o = 16; o; o >>= 1) s += __shfl_xor_sync(0xffffffffu, s, o);
    float lse = m + logf(s);
    float4 ov = { v0 - lse, v1 - lse, v2 - lse, v3 - lse };
    *(float4*)&out[i*HDIM + lane*4] = ov;
}

// ---------------- launch ----------------
extern "C" void kernel_launch(void* const* d_in, const int* in_sizes, int n_in,
                              void* d_out, int out_size) {
    const float* x  = (const float*)d_in[0];
    const int*   ei = (const int*)  d_in[1];
    const float* ew = (const float*)d_in[2];
    const float* wg[3] = {(const float*)d_in[3], (const float*)d_in[5], (const float*)d_in[7]};
    const float* bg[3] = {(const float*)d_in[4], (const float*)d_in[6], (const float*)d_in[8]};

    float *p_h, *p_n, *p_e, *p_RS, *p_wc, *p_bc;
    cudaGetSymbolAddress((void**)&p_h,  g_h);
    cudaGetSymbolAddress((void**)&p_n,  g_nbuf);
    cudaGetSymbolAddress((void**)&p_e,  g_e);
    cudaGetSymbolAddress((void**)&p_RS, g_RS);
    cudaGetSymbolAddress((void**)&p_wc, g_wc);
    cudaGetSymbolAddress((void**)&p_bc, g_bc);

    cudaFuncSetAttribute(k_knn_mma, cudaFuncAttributeMaxDynamicSharedMemorySize, KNN_SMEM);
    cudaFuncSetAttribute(k_edge,    cudaFuncAttributeMaxDynamicSharedMemorySize, EDGE_SMEM);

    // graph prep (once)
    k_deg_init<<<NNODES/256, 256>>>();
    k_deg<<<NEDGE/256, 256>>>(ei, ew);
    k_dis<<<NNODES/256, 256>>>();
    k_scan<<<1, 1024>>>();
    k_place<<<NEDGE/256, 256>>>(ei, ew);

    const float* cur = x;
    for (int L = 0; L < 3; L++) {
        float* nL = p_n + (size_t)L * NNODES * HDIM;
        float* eL = p_e + (size_t)L * NNODES * HDIM;
        const float* w1 = (const float*)d_in[9 + L*6 + 0];
        const float* b1 = (const float*)d_in[9 + L*6 + 1];
        const float* w2 = (const float*)d_in[9 + L*6 + 2];
        const float* b2 = (const float*)d_in[9 + L*6 + 3];
        const float* w3 = (const float*)d_in[9 + L*6 + 4];
        const float* b3 = (const float*)d_in[9 + L*6 + 5];

        // GCN: SIMT gemm + fused CSR aggregate/tanh/sn/split
        k_gemm<128,8,0><<<NNODES/128, 256>>>(cur, wg[L], nullptr, p_h, 128);
        k_gather<<<NNODES/8, 256>>>(bg[L], nL);

        // kNN: approx bf16 filter + exact fp32 refine
        k_knn_mma<<<dim3(NNODES/128, KSPL), 256, KNN_SMEM>>>();
        k_refine<<<NNODES/8, 256>>>(nL);

        // EdgeConv: combined-W1 RS gemm + fused HMMA MLP
        k_wcomb<<<16384/256, 256>>>(w1, b1);
        k_gemm<128,8,3><<<NNODES/128, 256>>>(nL, p_wc, p_bc, p_RS, 128);
        k_edge<<<NKR/128, 256, EDGE_SMEM>>>(p_RS, w2, b2, w3, b3, eL);

        cur = nL;
    }

    k_final<<<NNODES/8, 256>>>((float*)d_out);
}

// round 12
// speedup vs baseline: 1.5364x; 1.0940x over previous
#include <cuda_runtime.h>
#include <cuda_bf16.h>
#include <math.h>
#include <stdint.h>

#define NNODES 8192
#define HDIM   128
#define KNN    16
#define NEDGE  262144
#define NKR    (NNODES*KNN)
#define KSPL   2
#define CPS    (NNODES/KSPL)
#define TPC    (CPS/128)
#define QKEEP  16

// ---------------- scratch (device globals) ----------------
static __device__ float g_h[NNODES*HDIM];
static __device__ float g_nbuf[3][NNODES*HDIM];
static __device__ float g_sn[NNODES];
static __device__ float g_deg[NNODES];
static __device__ float g_dis[NNODES];
static __device__ int   g_knn[NKR];
static __device__ float g_e[3][NNODES*HDIM];
static __device__ int   g_pti[KSPL*NNODES*2*QKEEP];
static __device__ __nv_bfloat16 g_hi[NNODES*HDIM];
static __device__ __nv_bfloat16 g_lo[NNODES*HDIM];
static __device__ float g_RS[NNODES*128];
static __device__ float g_wc[128*128];
static __device__ float g_bc[128];
static __device__ __nv_bfloat16 g_w2h[128*64],  g_w2l[128*64];
static __device__ __nv_bfloat16 g_w3h[128*128], g_w3l[128*128];
// CSR
static __device__ int   g_cnt[NNODES];
static __device__ int   g_off[NNODES+1];
static __device__ int   g_cur[NNODES];
static __device__ int   g_esrc[NEDGE];
static __device__ float g_enrm[NEDGE];

// ---------------- helpers ----------------
__device__ __forceinline__ uint32_t smem_u32(const void* p) {
    uint32_t a;
    asm("{ .reg .u64 t; cvta.to.shared.u64 t, %1; cvt.u32.u64 %0, t; }" : "=r"(a) : "l"(p));
    return a;
}
__device__ __forceinline__ void ldm_x4(uint32_t* r, uint32_t addr) {
    asm volatile("ldmatrix.sync.aligned.m8n8.x4.shared.b16 {%0,%1,%2,%3}, [%4];"
        : "=r"(r[0]), "=r"(r[1]), "=r"(r[2]), "=r"(r[3]) : "r"(addr));
}
__device__ __forceinline__ void mma16816(float* c, const uint32_t* a, const uint32_t* b) {
    asm volatile("mma.sync.aligned.m16n8k16.row.col.f32.bf16.bf16.f32 "
        "{%0,%1,%2,%3}, {%4,%5,%6,%7}, {%8,%9}, {%0,%1,%2,%3};"
        : "+f"(c[0]), "+f"(c[1]), "+f"(c[2]), "+f"(c[3])
        : "r"(a[0]), "r"(a[1]), "r"(a[2]), "r"(a[3]), "r"(b[0]), "r"(b[1]));
}
__device__ __forceinline__ void cp16(uint32_t smaddr, const void* g) {
    asm volatile("cp.async.cg.shared.global [%0], [%1], 16;" :: "r"(smaddr), "l"(g));
}
#define CP_COMMIT() asm volatile("cp.async.commit_group;" ::: "memory")
#define CP_WAIT1()  asm volatile("cp.async.wait_group 1;" ::: "memory")
__device__ __forceinline__ __nv_bfloat162 split_hi2(float a, float b) {
    __nv_bfloat162 r; r.x = __float2bfloat16(a); r.y = __float2bfloat16(b); return r;
}
__device__ __forceinline__ __nv_bfloat162 split_lo2(float a, float b, __nv_bfloat162 h) {
    __nv_bfloat162 r;
    r.x = __float2bfloat16(a - __bfloat162float(h.x));
    r.y = __float2bfloat16(b - __bfloat162float(h.y));
    return r;
}

// ---------------- graph prep ----------------
__global__ void k_deg_init() {
    int i = blockIdx.x*blockDim.x + threadIdx.x;
    if (i < NNODES) { g_deg[i] = 1.0f; g_cnt[i] = 0; }
}
__global__ void k_deg(const int* __restrict__ ei, const float* __restrict__ ew) {
    int e = blockIdx.x*blockDim.x + threadIdx.x;
    if (e < NEDGE) {
        atomicAdd(&g_deg[ei[NEDGE + e]], ew[e]);
        atomicAdd(&g_cnt[ei[NEDGE + e]], 1);
    }
}
__global__ void k_dis() {
    int i = blockIdx.x*blockDim.x + threadIdx.x;
    if (i < NNODES) g_dis[i] = rsqrtf(g_deg[i]);
}
__global__ void k_scan() {
    __shared__ int ws[32];
    int t = threadIdx.x, lane = t & 31, w = t >> 5;
    int base = t*8;
    int v[8], s = 0;
    #pragma unroll
    for (int i = 0; i < 8; i++) { v[i] = s; s += g_cnt[base + i]; }
    int x = s;
    #pragma unroll
    for (int o = 1; o < 32; o <<= 1) {
        int y = __shfl_up_sync(0xffffffffu, x, o);
        if (lane >= o) x += y;
    }
    if (lane == 31) ws[w] = x;
    __syncthreads();
    if (w == 0) {
        int y = ws[lane];
        #pragma unroll
        for (int o = 1; o < 32; o <<= 1) {
            int z = __shfl_up_sync(0xffffffffu, y, o);
            if (lane >= o) y += z;
        }
        ws[lane] = y;
    }
    __syncthreads();
    int off = x - s + (w ? ws[w-1] : 0);
    #pragma unroll
    for (int i = 0; i < 8; i++) { g_off[base + i] = off + v[i]; g_cur[base + i] = off + v[i]; }
    if (t == 1023) g_off[NNODES] = off + s;
}
__global__ void k_place(const int* __restrict__ ei, const float* __restrict__ ew) {
    int e = blockIdx.x*blockDim.x + threadIdx.x;
    if (e < NEDGE) {
        int s = ei[e], d = ei[NEDGE + e];
        int slot = atomicAdd(&g_cur[d], 1);
        g_esrc[slot] = s;
        g_enrm[slot] = g_dis[s] * ew[e] * g_dis[d];
    }
}

// ---------------- fused GCN aggregate + tanh + sn + split ----------------
__global__ void __launch_bounds__(256) k_gather(const float* __restrict__ bg,
                                                float* __restrict__ out) {
    int wid = threadIdx.x >> 5, lane = threadIdx.x & 31;
    int node = blockIdx.x*8 + wid;
    int c = lane*4;
    float dsq = g_dis[node]; dsq *= dsq;
    float4 v = *(const float4*)&g_h[node*HDIM + c];
    v.x *= dsq; v.y *= dsq; v.z *= dsq; v.w *= dsq;
    int beg = g_off[node], end = g_off[node+1];
    int p = beg;
    for (; p + 3 < end; p += 4) {
        int s0 = g_esrc[p], s1 = g_esrc[p+1], s2 = g_esrc[p+2], s3 = g_esrc[p+3];
        float n0 = g_enrm[p], n1 = g_enrm[p+1], n2 = g_enrm[p+2], n3 = g_enrm[p+3];
        float4 h0 = *(const float4*)&g_h[s0*HDIM + c];
        float4 h1 = *(const float4*)&g_h[s1*HDIM + c];
        float4 h2 = *(const float4*)&g_h[s2*HDIM + c];
        float4 h3 = *(const float4*)&g_h[s3*HDIM + c];
        v.x += n0*h0.x + n1*h1.x + n2*h2.x + n3*h3.x;
        v.y += n0*h0.y + n1*h1.y + n2*h2.y + n3*h3.y;
        v.z += n0*h0.z + n1*h1.z + n2*h2.z + n3*h3.z;
        v.w += n0*h0.w + n1*h1.w + n2*h2.w + n3*h3.w;
    }
    for (; p < end; ++p) {
        int s = g_esrc[p];
        float nr = g_enrm[p];
        float4 hv = *(const float4*)&g_h[s*HDIM + c];
        v.x += nr*hv.x; v.y += nr*hv.y; v.z += nr*hv.z; v.w += nr*hv.w;
    }
    float4 b = *(const float4*)&bg[c];
    float t0 = tanhf(v.x + b.x), t1 = tanhf(v.y + b.y);
    float t2 = tanhf(v.z + b.z), t3 = tanhf(v.w + b.w);
    *(float4*)&out[node*HDIM + c] = make_float4(t0, t1, t2, t3);
    float ss = t0*t0 + t1*t1 + t2*t2 + t3*t3;
    #pragma unroll
    for (int o = 16; o; o >>= 1) ss += __shfl_xor_sync(0xffffffffu, ss, o);
    if (lane == 0) g_sn[node] = ss;
    __nv_bfloat162 h01 = split_hi2(t0, t1), h23 = split_hi2(t2, t3);
    __nv_bfloat162 l01 = split_lo2(t0, t1, h01), l23 = split_lo2(t2, t3, h23);
    *(__nv_bfloat162*)&g_hi[node*HDIM + c]     = h01;
    *(__nv_bfloat162*)&g_hi[node*HDIM + c + 2] = h23;
    *(__nv_bfloat162*)&g_lo[node*HDIM + c]     = l01;
    *(__nv_bfloat162*)&g_lo[node*HDIM + c + 2] = l23;
}

// ---------------- per-layer weight prep ----------------
__global__ void k_wcomb(const float* __restrict__ w1, const float* __restrict__ b1) {
    int i = blockIdx.x*blockDim.x + threadIdx.x;   // 16384
    int k = i >> 7, n = i & 127;
    float v = (n < 64) ? (w1[k*64 + n] - w1[(k + 128)*64 + n])
                       : w1[(k + 128)*64 + (n - 64)];
    g_wc[i] = v;
    if (i < 128) g_bc[i] = (i < 64) ? b1[i] : 0.f;
}
__global__ void k_wsplit(const float* __restrict__ w2, const float* __restrict__ w3) {
    int i = blockIdx.x*blockDim.x + threadIdx.x;   // 24576
    if (i < 8192) {
        int k = i >> 7, n = i & 127;
        float v = w2[i];
        __nv_bfloat16 h = __float2bfloat16(v);
        g_w2h[n*64 + k] = h;
        g_w2l[n*64 + k] = __float2bfloat16(v - __bfloat162float(h));
    } else {
        int j = i - 8192;
        int k = j >> 7, n = j & 127;
        float v = w3[j];
        __nv_bfloat16 h = __float2bfloat16(v);
        g_w3h[n*128 + k] = h;
        g_w3l[n*128 + k] = __float2bfloat16(v - __bfloat162float(h));
    }
}

// ---------------- top-K insertion ----------------
template<int NK>
__device__ __forceinline__ void topk_insert(float (&td)[NK], int (&ti)[NK], float d, int idx) {
    if (d >= td[NK-1]) return;
    #pragma unroll
    for (int p = NK-1; p > 0; --p) {
        bool sh = td[p-1] > d;
        float nd = sh ? td[p-1] : d;
        int   ni = sh ? ti[p-1] : idx;
        if (td[p] > d) { td[p] = nd; ti[p] = ni; }
    }
    if (td[0] > d) { td[0] = d; ti[0] = idx; }
}

// ---------------- approx kNN: cp.async double-buffered B ----------------
#define SSTR    136
#define TSB_B   34816
#define SM_AH   0
#define SM_B0   34816
#define SM_DIST 104448
#define SM_SNC  172032
#define KNN_SMEM 173568

__device__ __forceinline__ void load_tile_sync(char* sm, uint32_t ohi, int node0, int tid) {
    const uint4* HI = (const uint4*)g_hi;
    #pragma unroll
    for (int it = 0; it < 8; ++it) {
        int idx = tid + it*256;
        int row = idx >> 4;
        int c8  = idx & 15;
        uint32_t so = (uint32_t)(row*SSTR + c8*8)*2;
        size_t gi = ((size_t)(node0 + row)*HDIM + c8*8) >> 3;
        *(uint4*)(sm + ohi + so) = HI[gi];
    }
}
__device__ __forceinline__ void load_tile_cp(uint32_t smb, uint32_t ohi, int node0, int tid) {
    const char* HI = (const char*)g_hi;
    #pragma unroll
    for (int it = 0; it < 8; ++it) {
        int idx = tid + it*256;
        int row = idx >> 4;
        int c8  = idx & 15;
        uint32_t so = (uint32_t)(row*SSTR + c8*8)*2;
        cp16(smb + ohi + so, HI + ((size_t)(node0 + row)*HDIM + c8*8)*2);
    }
}

__global__ void __launch_bounds__(256) k_knn_mma() {
    extern __shared__ char sm[];
    const uint32_t smb = smem_u32(sm);
    const int tid = threadIdx.x, wid = tid >> 5, lane = tid & 31;
    const int wm = wid >> 1, wn = wid & 1;
    const int q0 = blockIdx.x * 128;
    const int c0 = blockIdx.y * CPS;

    // prefetch B0 + snc0, then load A synchronously (overlaps with async)
    load_tile_cp(smb, SM_B0, c0, tid);
    if (tid < 32) cp16(smb + SM_SNC + tid*16, &g_sn[c0 + tid*4]);
    CP_COMMIT();
    load_tile_sync(sm, SM_AH, q0, tid);

    float td[QKEEP]; int ti[QKEEP];
    #pragma unroll
    for (int j = 0; j < QKEEP; j++) { td[j] = 3.0e38f; ti[j] = 0; }

    const uint32_t a_off = (uint32_t)((32*wm + (lane & 15))*SSTR + (lane >> 4)*8) * 2;
    const uint32_t b_off = (uint32_t)((64*wn + (lane >> 4)*8 + (lane & 7))*SSTR
                                      + ((lane >> 3) & 1)*8) * 2;
    float* dist = (float*)(sm + SM_DIST);

    const int srow = tid >> 1;
    const int shalf = (tid & 1) * 64;

    for (int t = 0; t < TPC; ++t) {
        if (t + 1 < TPC) {
            load_tile_cp(smb, SM_B0 + ((t+1)&1)*TSB_B, c0 + (t+1)*128, tid);
            if (tid < 32) cp16(smb + SM_SNC + ((t+1)&1)*512 + tid*16,
                               &g_sn[c0 + (t+1)*128 + tid*4]);
        }
        CP_COMMIT();
        CP_WAIT1();          // B(t), snc(t) resident
        __syncthreads();     // also orders prior scan before dist overwrite

        float acc[2][8][4];
        #pragma unroll
        for (int mf = 0; mf < 2; mf++)
            #pragma unroll
            for (int nf = 0; nf < 8; nf++)
                #pragma unroll
                for (int v = 0; v < 4; v++) acc[mf][nf][v] = 0.f;

        const uint32_t abase = smb + SM_AH + a_off;
        const uint32_t bbase = smb + SM_B0 + (t&1)*TSB_B + b_off;
        #pragma unroll
        for (int ks = 0; ks < 8; ++ks) {
            uint32_t a0[4], a1[4];
            ldm_x4(a0, abase + ks*32);
            ldm_x4(a1, abase + ks*32 + 16*SSTR*2);
            #pragma unroll
            for (int nf = 0; nf < 4; ++nf) {
                uint32_t b[4];
                ldm_x4(b, bbase + ks*32 + nf*16*SSTR*2);
                mma16816(acc[0][nf*2],   a0, b);
                mma16816(acc[0][nf*2+1], a0, b + 2);
                mma16816(acc[1][nf*2],   a1, b);
                mma16816(acc[1][nf*2+1], a1, b + 2);
            }
        }

        {
            const int r0 = 32*wm + (lane >> 2);
            const int cb = 64*wn + (lane & 3)*2;
            #pragma unroll
            for (int mf = 0; mf < 2; mf++)
                #pragma unroll
                for (int nf = 0; nf < 8; nf++) {
                    float2 lo = { acc[mf][nf][0], acc[mf][nf][1] };
                    float2 hi = { acc[mf][nf][2], acc[mf][nf][3] };
                    *(float2*)&dist[(r0 + mf*16    )*132 + cb + nf*8] = lo;
                    *(float2*)&dist[(r0 + mf*16 + 8)*132 + cb + nf*8] = hi;
                }
        }
        __syncthreads();

        {
            const float* snc = (const float*)(sm + SM_SNC + (t&1)*512);
            const int cbase = c0 + t*128 + shalf;
            const float* dr = &dist[srow*132 + shalf];
            const float* sc = snc + shalf;
            float worst = td[QKEEP-1];
            #pragma unroll 4
            for (int c = 0; c < 64; c++) {
                float d = sc[c] - 2.0f*dr[c];
                if (d < worst) { topk_insert<QKEEP>(td, ti, d, cbase + c); worst = td[QKEEP-1]; }
            }
        }
    }

    {
        int q = q0 + srow;
        int base = (q*KSPL + blockIdx.y)*2*QKEEP + (tid & 1)*QKEEP;
        #pragma unroll
        for (int j = 0; j < QKEEP; j++)
            g_pti[base + j] = ti[j];
    }
}

// ---------------- exact refine ----------------
__global__ void __launch_bounds__(256) k_refine(const float* __restrict__ X) {
    int wid = threadIdx.x >> 5, lane = threadIdx.x & 31;
    int q = blockIdx.x*8 + wid;
    float4 xi = *(const float4*)&X[(size_t)q*HDIM + lane*4];
    float dloc[2]; int iloc[2];
    dloc[0] = dloc[1] = 3.0e38f;
    iloc[0] = iloc[1] = 0x7fffffff;
    #pragma unroll 4
    for (int c = 0; c < KSPL*2*QKEEP; c++) {
        int j = g_pti[q*KSPL*2*QKEEP + c];
        float4 xj = *(const float4*)&X[(size_t)j*HDIM + lane*4];
        float p = xi.x*xj.x + xi.y*xj.y + xi.z*xj.z + xi.w*xj.w;
        #pragma unroll
        for (int o = 16; o; o >>= 1) p += __shfl_xor_sync(0xffffffffu, p, o);
        float d = g_sn[j] - 2.0f*p;
        if (lane == (c & 31)) { dloc[c >> 5] = d; iloc[c >> 5] = j; }
    }
    for (int r = 0; r < KNN; r++) {
        float d = dloc[0]; int idx = iloc[0]; int sl = 0;
        if (dloc[1] < d || (dloc[1] == d && iloc[1] < idx)) { d = dloc[1]; idx = iloc[1]; sl = 1; }
        float dw = d; int iw = idx;
        #pragma unroll
        for (int o = 16; o; o >>= 1) {
            float od = __shfl_xor_sync(0xffffffffu, dw, o);
            int   oi = __shfl_xor_sync(0xffffffffu, iw, o);
            if (od < dw || (od == dw && oi < iw)) { dw = od; iw = oi; }
        }
        if (d == dw && idx == iw) dloc[sl] = 3.0e38f;
        if (lane == 0) g_knn[q*KNN + r] = iw;
    }
}

// ---------------- fused EdgeConv MLP (pre-split weights) ----------------
#define ESTR1    72
#define ESTR2    136
#define SM_A1H   0
#define SM_A1L   18432
#define SM_W2H   36864
#define SM_W2L   55296
#define SM_W3H   0
#define SM_W3L   34816
#define SM_A2H   73728
#define SM_A2L   108544
#define SM_JIDX  143360
#define EDGE_SMEM (143360 + 512)

__global__ void __launch_bounds__(256) k_edge(
        const float* __restrict__ RS,
        const float* __restrict__ b2, const float* __restrict__ b3,
        float* __restrict__ E)
{
    extern __shared__ char sm[];
    const uint32_t smb = smem_u32(sm);
    const int tid = threadIdx.x, wid = tid >> 5, lane = tid & 31;
    const int wm = wid >> 1, wn = wid & 1;
    const int r0 = blockIdx.x * 128;
    int* jidx = (int*)(sm + SM_JIDX);

    if (tid < 128) jidx[tid] = g_knn[r0 + tid];

    // W2 hi/lo: plain 16B copies (pre-split in gmem, [n][64] layout)
    {
        const uint4* H = (const uint4*)g_w2h;
        const uint4* L = (const uint4*)g_w2l;
        #pragma unroll
        for (int i = 0; i < 4; i++) {
            int e = tid + i*256;                 // 1024 uint4
            int n = e >> 3, kc = e & 7;
            uint32_t so = (uint32_t)(n*ESTR1 + kc*8)*2;
            *(uint4*)(sm + SM_W2H + so) = H[e];
            *(uint4*)(sm + SM_W2L + so) = L[e];
        }
    }
    __syncthreads();

    {
        __nv_bfloat16* A1H = (__nv_bfloat16*)(sm + SM_A1H);
        __nv_bfloat16* A1L = (__nv_bfloat16*)(sm + SM_A1L);
        int row = tid >> 1;
        int cb = (tid & 1) * 32;
        int i = (r0 + row) >> 4;
        int j = jidx[row];
        const float* Ri = &RS[(size_t)i*128 + cb];
        const float* Sj = &RS[(size_t)j*128 + 64 + cb];
        #pragma unroll
        for (int c = 0; c < 32; c += 4) {
            float4 rv = *(const float4*)(Ri + c);
            float4 sv = *(const float4*)(Sj + c);
            float h0 = fmaxf(rv.x + sv.x, 0.f), h1 = fmaxf(rv.y + sv.y, 0.f);
            float h2 = fmaxf(rv.z + sv.z, 0.f), h3 = fmaxf(rv.w + sv.w, 0.f);
            __nv_bfloat162 a01 = split_hi2(h0, h1), a23 = split_hi2(h2, h3);
            *(__nv_bfloat162*)&A1H[row*ESTR1 + cb + c]     = a01;
            *(__nv_bfloat162*)&A1H[row*ESTR1 + cb + c + 2] = a23;
            *(__nv_bfloat162*)&A1L[row*ESTR1 + cb + c]     = split_lo2(h0, h1, a01);
            *(__nv_bfloat162*)&A1L[row*ESTR1 + cb + c + 2] = split_lo2(h2, h3, a23);
        }
    }
    __syncthreads();

    const uint32_t a_off2 = (uint32_t)((32*wm + (lane & 15))*ESTR1 + (lane >> 4)*8) * 2;
    const uint32_t b_off2 = (uint32_t)((64*wn + (lane >> 4)*8 + (lane & 7))*ESTR1
                                       + ((lane >> 3) & 1)*8) * 2;

    float acc[2][8][4];
    #pragma unroll
    for (int mf = 0; mf < 2; mf++)
        #pragma unroll
        for (int nf = 0; nf < 8; nf++)
            #pragma unroll
            for (int v = 0; v < 4; v++) acc[mf][nf][v] = 0.f;

    #pragma unroll
    for (int term = 0; term < 3; ++term) {
        const uint32_t abase = smb + (term == 2 ? SM_A1L : SM_A1H) + a_off2;
        const uint32_t bbase = smb + (term == 1 ? SM_W2L : SM_W2H) + b_off2;
        #pragma unroll
        for (int ks = 0; ks < 4; ++ks) {
            uint32_t a0[4], a1[4];
            ldm_x4(a0, abase + ks*32);
            ldm_x4(a1, abase + ks*32 + 16*ESTR1*2);
            #pragma unroll
            for (int nf = 0; nf < 4; ++nf) {
                uint32_t b[4];
                ldm_x4(b, bbase + ks*32 + nf*16*ESTR1*2);
                mma16816(acc[0][nf*2],   a0, b);
                mma16816(acc[0][nf*2+1], a0, b + 2);
                mma16816(acc[1][nf*2],   a1, b);
                mma16816(acc[1][nf*2+1], a1, b + 2);
            }
        }
    }
    __syncthreads();

    {
        __nv_bfloat16* A2H = (__nv_bfloat16*)(sm + SM_A2H);
        __nv_bfloat16* A2L = (__nv_bfloat16*)(sm + SM_A2L);
        const int re = 32*wm + (lane >> 2);
        const int ce = 64*wn + (lane & 3)*2;
        #pragma unroll
        for (int mf = 0; mf < 2; mf++)
            #pragma unroll
            for (int nf = 0; nf < 8; nf++) {
                int r = re + mf*16;
                int c = ce + nf*8;
                float v0 = fmaxf(acc[mf][nf][0] + b2[c],   0.f);
                float v1 = fmaxf(acc[mf][nf][1] + b2[c+1], 0.f);
                float v2 = fmaxf(acc[mf][nf][2] + b2[c],   0.f);
                float v3 = fmaxf(acc[mf][nf][3] + b2[c+1], 0.f);
                __nv_bfloat162 h01 = split_hi2(v0, v1), h23 = split_hi2(v2, v3);
                *(__nv_bfloat162*)&A2H[r*ESTR2 + c]       = h01;
                *(__nv_bfloat162*)&A2L[r*ESTR2 + c]       = split_lo2(v0, v1, h01);
                *(__nv_bfloat162*)&A2H[(r+8)*ESTR2 + c]   = h23;
                *(__nv_bfloat162*)&A2L[(r+8)*ESTR2 + c]   = split_lo2(v2, v3, h23);
            }
    }
    // W3 hi/lo copies ([n][128] layout)
    {
        const uint4* H = (const uint4*)g_w3h;
        const uint4* L = (const uint4*)g_w3l;
        #pragma unroll
        for (int i = 0; i < 8; i++) {
            int e = tid + i*256;                 // 2048 uint4
            int n = e >> 4, kc = e & 15;
            uint32_t so = (uint32_t)(n*ESTR2 + kc*8)*2;
            *(uint4*)(sm + SM_W3H + so) = H[e];
            *(uint4*)(sm + SM_W3L + so) = L[e];
        }
    }
    __syncthreads();

    #pragma unroll
    for (int mf = 0; mf < 2; mf++)
        #pragma unroll
        for (int nf = 0; nf < 8; nf++)
            #pragma unroll
            for (int v = 0; v < 4; v++) acc[mf][nf][v] = 0.f;

    const uint32_t a_off3 = (uint32_t)((32*wm + (lane & 15))*ESTR2 + (lane >> 4)*8) * 2;
    const uint32_t b_off3 = (uint32_t)((64*wn + (lane >> 4)*8 + (lane & 7))*ESTR2
                                       + ((lane >> 3) & 1)*8) * 2;
    #pragma unroll
    for (int term = 0; term < 3; ++term) {
        const uint32_t abase = smb + (term == 2 ? SM_A2L : SM_A2H) + a_off3;
        const uint32_t bbase = smb + (term == 1 ? SM_W3L : SM_W3H) + b_off3;
        #pragma unroll
        for (int ks = 0; ks < 8; ++ks) {
            uint32_t a0[4], a1[4];
            ldm_x4(a0, abase + ks*32);
            ldm_x4(a1, abase + ks*32 + 16*ESTR2*2);
            #pragma unroll
            for (int nf = 0; nf < 4; ++nf) {
                uint32_t b[4];
                ldm_x4(b, bbase + ks*32 + nf*16*ESTR2*2);
                mma16816(acc[0][nf*2],   a0, b);
                mma16816(acc[0][nf*2+1], a0, b + 2);
                mma16816(acc[1][nf*2],   a1, b);
                mma16816(acc[1][nf*2+1], a1, b + 2);
            }
        }
    }

    {
        const int ce = 64*wn + (lane & 3)*2;
        #pragma unroll
        for (int mf = 0; mf < 2; mf++) {
            int node = blockIdx.x*8 + 2*wm + mf;
            #pragma unroll
            for (int nf = 0; nf < 8; nf++) {
                float v0 = fmaxf(acc[mf][nf][0], acc[mf][nf][2]);
                float v1 = fmaxf(acc[mf][nf][1], acc[mf][nf][3]);
                #pragma unroll
                for (int o = 4; o < 32; o <<= 1) {
                    v0 = fmaxf(v0, __shfl_xor_sync(0xffffffffu, v0, o));
                    v1 = fmaxf(v1, __shfl_xor_sync(0xffffffffu, v1, o));
                }
                if ((lane >> 2) == 0) {
                    int c = ce + nf*8;
                    E[(size_t)node*128 + c]     = v0 + b3[c];
                    E[(size_t)node*128 + c + 1] = v1 + b3[c+1];
                }
            }
        }
    }
}

// ---------------- SIMT SGEMM BM=64 (GCN + combined RS), K=128, BN=128 ----------------
// EPI: 0 plain, 3 bias
template<int EPI>
__global__ __launch_bounds__(256) void k_gemm64(const float* __restrict__ A,
        const float* __restrict__ B, const float* __restrict__ bias,
        float* __restrict__ C)
{
    __shared__ float As[16][68];
    __shared__ float Bs[16][132];
    const int tid = threadIdx.x;
    const int tx = tid & 15, ty = tid >> 4;
    const int r0 = blockIdx.x * 64;

    float acc[4][8];
    #pragma unroll
    for (int m = 0; m < 4; m++)
        #pragma unroll
        for (int n = 0; n < 8; n++) acc[m][n] = 0.f;

    for (int kb = 0; kb < 128; kb += 16) {
        {
            int r = tid >> 2, c4 = tid & 3;
            float4 v = *(const float4*)&A[(size_t)(r0 + r)*128 + kb + c4*4];
            As[c4*4+0][r] = v.x; As[c4*4+1][r] = v.y;
            As[c4*4+2][r] = v.z; As[c4*4+3][r] = v.w;
        }
        #pragma unroll
        for (int i = 0; i < 2; i++) {
            int f = tid + i*256;
            int r = f >> 5, c4 = f & 31;
            *(float4*)&Bs[r][c4*4] = *(const float4*)&B[(size_t)(kb + r)*128 + c4*4];
        }
        __syncthreads();
        #pragma unroll
        for (int kk = 0; kk < 16; kk++) {
            float a[4], b[8];
            *(float4*)&a[0] = *(const float4*)&As[kk][ty*4];
            *(float4*)&b[0] = *(const float4*)&Bs[kk][tx*8];
            *(float4*)&b[4] = *(const float4*)&Bs[kk][tx*8 + 4];
            #pragma unroll
            for (int m = 0; m < 4; m++)
                #pragma unroll
                for (int n = 0; n < 8; n++) acc[m][n] += a[m] * b[n];
        }
        __syncthreads();
    }

    #pragma unroll
    for (int m = 0; m < 4; m++) {
        size_t r = r0 + ty*4 + m;
        #pragma unroll
        for (int n = 0; n < 8; n += 4) {
            float4 v;
            v.x = acc[m][n]; v.y = acc[m][n+1]; v.z = acc[m][n+2]; v.w = acc[m][n+3];
            if constexpr (EPI == 3) {
                int c = tx*8 + n;
                v.x += bias[c]; v.y += bias[c+1]; v.z += bias[c+2]; v.w += bias[c+3];
            }
            *(float4*)&C[r*128 + tx*8 + n] = v;
        }
    }
}

// ---------------- final: fused rownorm + product + log_softmax ----------------
__global__ void k_final(float* __restrict__ out) {
    int w = threadIdx.x >> 5, lane = threadIdx.x & 31;
    int i = blockIdx.x*8 + w;
    float4 e1 = *(const float4*)&g_e[0][i*HDIM + lane*4];
    float4 n1 = *(const float4*)&g_nbuf[0][i*HDIM + lane*4];
    float a = e1.x + n1.x, b = e1.y + n1.y, c = e1.z + n1.z, d = e1.w + n1.w;
    float s1 = a*a + b*b + c*c + d*d;
    #pragma unroll
    for (int o = 16; o; o >>= 1) s1 += __shfl_xor_sync(0xffffffffu, s1, o);
    float r = sqrtf(s1);

    float4 e2 = *(const float4*)&g_e[1][i*HDIM + lane*4];
    float4 n2 = *(const float4*)&g_nbuf[1][i*HDIM + lane*4];
    float4 e3 = *(const float4*)&g_e[2][i*HDIM + lane*4];
    float4 n3 = *(const float4*)&g_nbuf[2][i*HDIM + lane*4];
    float v0 = r * (e2.x + n2.x) * (e3.x + n3.x);
    float v1 = r * (e2.y + n2.y) * (e3.y + n3.y);
    float v2 = r * (e2.z + n2.z) * (e3.z + n3.z);
    float v3 = r * (e2.w + n2.w) * (e3.w + n3.w);
    float m = fmaxf(fmaxf(v0, v1), fmaxf(v2, v3));
    #pragma unroll
    for (int o = 16; o; o >>= 1) m = fmaxf(m, __shfl_xor_sync(0xffffffffu, m, o));
    float s = expf(v0 - m) + expf(v1 - m) + expf(v2 - m) + expf(v3 - m);
    #pragma unroll
    for (int o = 16; o; o >>= 1) s += __shfl_xor_sync(0xffffffffu, s, o);
    float lse = m + logf(s);
    float4 ov = { v0 - lse, v1 - lse, v2 - lse, v3 - lse };
    *(float4*)&out[i*HDIM + lane*4] = ov;
}

// ---------------- launch ----------------
extern "C" void kernel_launch(void* const* d_in, const int* in_sizes, int n_in,
                              void* d_out, int out_size) {
    const float* x  = (const float*)d_in[0];
    const int*   ei = (const int*)  d_in[1];
    const float* ew = (const float*)d_in[2];
    const float* wg[3] = {(const float*)d_in[3], (const float*)d_in[5], (const float*)d_in[7]};
    const float* bg[3] = {(const float*)d_in[4], (const float*)d_in[6], (const float*)d_in[8]};

    float *p_h, *p_n, *p_e, *p_RS, *p_wc, *p_bc;
    cudaGetSymbolAddress((void**)&p_h,  g_h);
    cudaGetSymbolAddress((void**)&p_n,  g_nbuf);
    cudaGetSymbolAddress((void**)&p_e,  g_e);
    cudaGetSymbolAddress((void**)&p_RS, g_RS);
    cudaGetSymbolAddress((void**)&p_wc, g_wc);
    cudaGetSymbolAddress((void**)&p_bc, g_bc);

    cudaFuncSetAttribute(k_knn_mma, cudaFuncAttributeMaxDynamicSharedMemorySize, KNN_SMEM);
    cudaFuncSetAttribute(k_edge,    cudaFuncAttributeMaxDynamicSharedMemorySize, EDGE_SMEM);

    // graph prep (once)
    k_deg_init<<<NNODES/256, 256>>>();
    k_deg<<<NEDGE/256, 256>>>(ei, ew);
    k_dis<<<NNODES/256, 256>>>();
    k_scan<<<1, 1024>>>();
    k_place<<<NEDGE/256, 256>>>(ei, ew);

    const float* cur = x;
    for (int L = 0; L < 3; L++) {
        float* nL = p_n + (size_t)L * NNODES * HDIM;
        float* eL = p_e + (size_t)L * NNODES * HDIM;
        const float* w1 = (const float*)d_in[9 + L*6 + 0];
        const float* b1 = (const float*)d_in[9 + L*6 + 1];
        const float* w2 = (const float*)d_in[9 + L*6 + 2];
        const float* b2 = (const float*)d_in[9 + L*6 + 3];
        const float* w3 = (const float*)d_in[9 + L*6 + 4];
        const float* b3 = (const float*)d_in[9 + L*6 + 5];

        // GCN: SIMT gemm (BM=64) + fused CSR aggregate/tanh/sn/split
        k_gemm64<0><<<NNODES/64, 256>>>(cur, wg[L], nullptr, p_h);
        k_gather<<<NNODES/8, 256>>>(bg[L], nL);

        // kNN: approx bf16 filter (cp.async pipelined) + exact fp32 refine
        k_knn_mma<<<dim3(NNODES/128, KSPL), 256, KNN_SMEM>>>();
        k_refine<<<NNODES/8, 256>>>(nL);

        // EdgeConv: weight prep + RS gemm + fused HMMA MLP
        k_wcomb<<<16384/256, 256>>>(w1, b1);
        k_wsplit<<<24576/256, 256>>>(w2, w3);
        k_gemm64<3><<<NNODES/64, 256>>>(nL, p_wc, p_bc, p_RS);
        k_edge<<<NKR/128, 256, EDGE_SMEM>>>(p_RS, b2, b3, eL);

        cur = nL;
    }

    k_final<<<NNODES/8, 256>>>((float*)d_out);
}